// round 13
// baseline (speedup 1.0000x reference)
#include <cuda_runtime.h>
#include <cuda_fp16.h>
#include <cstdint>

typedef __half f16;

constexpr int BSZ = 8, SEQ = 2048, DIM = 768;
constexpr int MTOT = BSZ * SEQ;            // 16384

// Swizzled smem tiles. BK=32: 64B rows (TILE 8KB). BK=64: 128B rows (16KB).
constexpr int TILE  = 8192;
constexpr int STB3  = 4 * TILE;            // 32768: Ah,Al,Bh,Bl (BK=32)
constexpr int SMEMSZ3 = 3 * STB3;          // 98304 (3-stage)
constexpr int SMEMSZ1 = 3 * 32768;         // 98304 (PV: BK=64, 2 tiles, 3-stage)
// proj epi2 staging needs 128*129*4 = 66048 <= both

// ---------------- static device scratch (allocation-free rule) --------------
__device__ f16 g_xh[(size_t)MTOT * DIM];
__device__ f16 g_xl[(size_t)MTOT * DIM];
__device__ f16 g_wth[3][DIM * DIM];        // contiguous [2304 x 768] B^T
__device__ f16 g_wtl[3][DIM * DIM];
__device__ f16 g_qh[(size_t)MTOT * DIM];
__device__ f16 g_ql[(size_t)MTOT * DIM];
__device__ f16 g_kh[(size_t)MTOT * DIM];
__device__ f16 g_kl[(size_t)MTOT * DIM];
__device__ f16 g_vth[(size_t)MTOT * DIM];   // V^T per batch: [b][768][2048], hi only
__device__ float g_s[(size_t)BSZ * SEQ * SEQ];
__device__ f16 g_ph[(size_t)BSZ * SEQ * SEQ];

// ---------------- PTX helpers ----------------------------------------------
__device__ __forceinline__ uint32_t smem_u32(const void* p) {
    uint32_t a;
    asm("{ .reg .u64 t; cvta.to.shared.u64 t, %1; cvt.u32.u64 %0, t; }"
        : "=r"(a) : "l"(p));
    return a;
}

__device__ __forceinline__ void ldmx4(uint32_t* r, uint32_t a) {
    asm volatile("ldmatrix.sync.aligned.m8n8.x4.shared.b16 {%0,%1,%2,%3}, [%4];"
                 : "=r"(r[0]), "=r"(r[1]), "=r"(r[2]), "=r"(r[3]) : "r"(a));
}

__device__ __forceinline__ void mma_f16(float* c, const uint32_t* a, const uint32_t* b) {
    asm volatile(
        "mma.sync.aligned.m16n8k16.row.col.f32.f16.f16.f32 "
        "{%0,%1,%2,%3}, {%4,%5,%6,%7}, {%8,%9}, {%0,%1,%2,%3};"
        : "+f"(c[0]), "+f"(c[1]), "+f"(c[2]), "+f"(c[3])
        : "r"(a[0]), "r"(a[1]), "r"(a[2]), "r"(a[3]), "r"(b[0]), "r"(b[1]));
}

__device__ __forceinline__ void cpasync16(uint32_t s, const void* g) {
    asm volatile("cp.async.cg.shared.global [%0], [%1], 16;" :: "r"(s), "l"(g));
}

// Generic swizzled in-tile offset. CPR = 16B-chunks per row (4 for BK=32, 8 for BK=64).
template <int CPR>
__device__ __forceinline__ uint32_t swzg(int row, int ch) {
    return (uint32_t)(row * (CPR * 16) +
                      (((ch ^ ((row * CPR) >> 3)) & (CPR - 1)) << 4));
}

// ---------------------------------------------------------------------------
// Fused QKV projection (BK=32).  Grid (18, 128); n0 selects output+passes:
//   n0 <  768 : Q hi/lo (3-pass)   n0 < 1536 : K hi/lo (3-pass)
//   else      : V^T hi  (2-pass)
// 3-stage cp.async pipeline, 128 threads, 2 CTAs/SM.
// ---------------------------------------------------------------------------
__global__ void __launch_bounds__(128, 2)
proj_fused(const f16* __restrict__ Ah, const f16* __restrict__ Al,
           const f16* __restrict__ Bh, const f16* __restrict__ Bl,
           f16* __restrict__ Qh, f16* __restrict__ Ql,
           f16* __restrict__ Kh, f16* __restrict__ Kl,
           f16* __restrict__ Vt)
{
    extern __shared__ char smem[];
    const int tid = threadIdx.x, lane = tid & 31, wid = tid >> 5;
    const int m0 = blockIdx.y * 128, n0 = blockIdx.x * 128;
    const int warp_m = wid & 1, warp_n = wid >> 1;
    const bool three = (n0 < 1536);

    const char* pAh = (const char*)Ah;
    const char* pAl = (const char*)Al;
    const char* pBh = (const char*)Bh;
    const char* pBl = (const char*)Bl;

    const uint32_t sb = smem_u32(smem);
    const uint32_t rowbytes = DIM * 2;

    float acc[4][8][4];
#pragma unroll
    for (int t = 0; t < 4; t++)
#pragma unroll
        for (int j = 0; j < 8; j++)
#pragma unroll
            for (int c = 0; c < 4; c++) acc[t][j][c] = 0.0f;

#define PISSUE(kc, buf)                                                          \
    {                                                                            \
        uint32_t s0 = sb + (buf) * STB3;                                         \
        uint32_t kcb = (uint32_t)(kc) * 64;                                      \
        _Pragma("unroll")                                                        \
        for (int i = 0; i < 4; i++) {                                            \
            int c = tid + i * 128;                                               \
            int r = c >> 2, ch = c & 3;                                          \
            size_t goA = (size_t)(m0 + r) * rowbytes + kcb + ch * 16;            \
            size_t goB = (size_t)(n0 + r) * rowbytes + kcb + ch * 16;            \
            uint32_t so = swzg<4>(r, ch);                                        \
            cpasync16(s0 + 0 * TILE + so, pAh + goA);                            \
            cpasync16(s0 + 1 * TILE + so, pAl + goA);                            \
            cpasync16(s0 + 2 * TILE + so, pBh + goB);                            \
            if (three) cpasync16(s0 + 3 * TILE + so, pBl + goB);                 \
        }                                                                        \
        asm volatile("cp.async.commit_group;" ::: "memory");                     \
    }

    PISSUE(0, 0);
    PISSUE(1, 1);

    const int nch = DIM >> 5;   // 24
    int cb = 0, ib = 2;
    for (int kc = 0; kc < nch; kc++) {
        asm volatile("cp.async.wait_group 1;" ::: "memory");
        __syncthreads();

        const int knext = kc + 2;
        if (knext < nch) PISSUE(knext, ib);
        ib = (ib + 1 == 3) ? 0 : ib + 1;

        const uint32_t sA = sb + cb * STB3;
        cb = (cb + 1 == 3) ? 0 : cb + 1;

#pragma unroll
        for (int ks = 0; ks < 2; ks++) {
            uint32_t afh[4][4], afl[4][4];

            const int ra0 = warp_m * 64 + (lane & 15);
            const int ca = ks * 2 + (lane >> 4);
#pragma unroll
            for (int t = 0; t < 4; t++) {
                uint32_t ad = sA + swzg<4>(ra0 + t * 16, ca);
                ldmx4(afh[t], ad);
                ldmx4(afl[t], ad + TILE);
            }

            const int rb0 = warp_n * 64 + (lane >> 4) * 8 + (lane & 7);
            const int cbk = ks * 2 + ((lane >> 3) & 1);
#pragma unroll
            for (int jp = 0; jp < 4; jp++) {
                uint32_t bd = sA + 2 * TILE + swzg<4>(rb0 + jp * 16, cbk);
                uint32_t rh[4];
                ldmx4(rh, bd);
                const int j0 = jp * 2, j1 = jp * 2 + 1;
#pragma unroll
                for (int t = 0; t < 4; t++) {
                    mma_f16(acc[t][j0], afh[t], rh + 0);
                    mma_f16(acc[t][j1], afh[t], rh + 2);
                }
                if (three) {
                    uint32_t rl[4];
                    ldmx4(rl, bd + TILE);
#pragma unroll
                    for (int t = 0; t < 4; t++) {
                        mma_f16(acc[t][j0], afh[t], rl + 0);
                        mma_f16(acc[t][j1], afh[t], rl + 2);
                    }
                }
#pragma unroll
                for (int t = 0; t < 4; t++) {
                    mma_f16(acc[t][j0], afl[t], rh + 0);
                    mma_f16(acc[t][j1], afl[t], rh + 2);
                }
            }
        }
        __syncthreads();
    }
#undef PISSUE

    // ---------------- epilogue dispatch ----------------
    const int rbase = warp_m * 64 + (lane >> 2);
    const int cbase = warp_n * 64 + (lane & 3) * 2;

    if (three) {
        f16* Oh = (n0 < 768) ? Qh : Kh;
        f16* Ol = (n0 < 768) ? Ql : Kl;
        const int nc0 = (n0 < 768) ? n0 : n0 - 768;
#pragma unroll
        for (int t = 0; t < 4; t++)
#pragma unroll
            for (int j = 0; j < 8; j++)
#pragma unroll
                for (int h = 0; h < 2; h++) {
                    int rr = m0 + rbase + t * 16 + h * 8;
                    int cc = nc0 + cbase + j * 8;
                    float x0 = acc[t][j][h * 2 + 0], x1 = acc[t][j][h * 2 + 1];
                    f16 h0 = __float2half(x0), h1 = __float2half(x1);
                    f16 l0 = __float2half(x0 - __half2float(h0));
                    f16 l1 = __float2half(x1 - __half2float(h1));
                    *(__half2*)(Oh + (size_t)rr * DIM + cc) = __halves2half2(h0, h1);
                    *(__half2*)(Ol + (size_t)rr * DIM + cc) = __halves2half2(l0, l1);
                }
    } else {
        float* st = (float*)smem;
#pragma unroll
        for (int t = 0; t < 4; t++)
#pragma unroll
            for (int j = 0; j < 8; j++)
#pragma unroll
                for (int h = 0; h < 2; h++) {
                    int rr = rbase + t * 16 + h * 8;
                    int cc = cbase + j * 8;
                    st[(size_t)rr * 129 + cc + 0] = acc[t][j][h * 2 + 0];
                    st[(size_t)rr * 129 + cc + 1] = acc[t][j][h * 2 + 1];
                }
        __syncthreads();
        const int nv0 = n0 - 1536;
        for (int idx = tid; idx < 128 * 128; idx += 128) {
            int nl = idx >> 7, ml = idx & 127;
            int mg = m0 + ml;
            int b = mg >> 11, mloc = mg & 2047;
            float x = st[(size_t)ml * 129 + nl];
            size_t o = (size_t)b * DIM * SEQ + (size_t)(nv0 + nl) * SEQ + mloc;
            Vt[o] = __float2half(x);
        }
    }
}

// ---------------------------------------------------------------------------
// Batched GEMM.  NPASS=3: BK=32, 4 tiles/stage, 3-stage (scores).
//                NPASS=1: BK=64, 2 tiles/stage, 3-stage (PV).
// 128 threads, tile 128x128, warp tile 64x64, 2 CTAs/SM, fp32 out.
// ---------------------------------------------------------------------------
template <int NPASS, int NSTAGE, int BK>
__global__ void __launch_bounds__(128, 2)
gemm_mma(const f16* __restrict__ Ah, const f16* __restrict__ Al,
         const f16* __restrict__ Bh, const f16* __restrict__ Bl,
         float* __restrict__ O,
         int K, long batchA, long batchB, long batchC, int ldC)
{
    constexpr int CPR   = BK / 8;              // 16B chunks per row
    constexpr int TK    = 128 * BK * 2;        // tile bytes
    constexpr int NT    = (NPASS == 3) ? 4 : 2;
    constexpr int STB   = NT * TK;
    constexpr int BOFF  = (NPASS == 3) ? 2 * TK : TK;
    constexpr int NKS   = BK / 16;

    extern __shared__ char smem[];
    const int tid = threadIdx.x, lane = tid & 31, wid = tid >> 5;
    const int z = blockIdx.z;
    const int m0 = blockIdx.y * 128, n0 = blockIdx.x * 128;
    const int warp_m = wid & 1, warp_n = wid >> 1;

    const char* pAh = (const char*)(Ah + (size_t)z * batchA);
    const char* pAl = (NPASS == 3) ? (const char*)(Al + (size_t)z * batchA) : nullptr;
    const char* pBh = (const char*)(Bh + (size_t)z * batchB);
    const char* pBl = (NPASS == 3) ? (const char*)(Bl + (size_t)z * batchB) : nullptr;

    const uint32_t sb = smem_u32(smem);
    const uint32_t rowbytes = (uint32_t)K * 2;

    float acc[4][8][4];
#pragma unroll
    for (int t = 0; t < 4; t++)
#pragma unroll
        for (int j = 0; j < 8; j++)
#pragma unroll
            for (int c = 0; c < 4; c++) acc[t][j][c] = 0.0f;

    const int nch = K / BK;

#define ISSUE(kc, buf)                                                           \
    {                                                                            \
        uint32_t s0 = sb + (buf) * STB;                                          \
        uint32_t kcb = (uint32_t)(kc) * (BK * 2);                                \
        _Pragma("unroll")                                                        \
        for (int i = 0; i < CPR; i++) {                                          \
            int c = tid + i * 128;                                               \
            int r = c / CPR, ch = c % CPR;                                       \
            size_t goA = (size_t)(m0 + r) * rowbytes + kcb + ch * 16;            \
            size_t goB = (size_t)(n0 + r) * rowbytes + kcb + ch * 16;            \
            uint32_t so = swzg<CPR>(r, ch);                                      \
            cpasync16(s0 + so, pAh + goA);                                       \
            if (NPASS == 3) cpasync16(s0 + TK + so, pAl + goA);                  \
            cpasync16(s0 + BOFF + so, pBh + goB);                                \
            if (NPASS == 3) cpasync16(s0 + 3 * TK + so, pBl + goB);              \
        }                                                                        \
        asm volatile("cp.async.commit_group;" ::: "memory");                     \
    }

#pragma unroll
    for (int p = 0; p < NSTAGE - 1; p++) ISSUE(p, p);

    int cb = 0, ib = NSTAGE - 1;
    for (int kc = 0; kc < nch; kc++) {
        asm volatile("cp.async.wait_group %0;" :: "n"(NSTAGE - 2) : "memory");
        __syncthreads();

        const int knext = kc + NSTAGE - 1;
        if (knext < nch) ISSUE(knext, ib);
        ib = (ib + 1 == NSTAGE) ? 0 : ib + 1;

        const uint32_t sA = sb + cb * STB;
        cb = (cb + 1 == NSTAGE) ? 0 : cb + 1;

#pragma unroll
        for (int ks = 0; ks < NKS; ks++) {
            uint32_t afh[4][4], afl[4][4];

            const int ra0 = warp_m * 64 + (lane & 15);
            const int ca = ks * 2 + (lane >> 4);
#pragma unroll
            for (int t = 0; t < 4; t++) {
                uint32_t ad = sA + swzg<CPR>(ra0 + t * 16, ca);
                ldmx4(afh[t], ad);
                if (NPASS == 3) ldmx4(afl[t], ad + TK);
            }

            const int rb0 = warp_n * 64 + (lane >> 4) * 8 + (lane & 7);
            const int cbk = ks * 2 + ((lane >> 3) & 1);
#pragma unroll
            for (int jp = 0; jp < 4; jp++) {
                uint32_t bd = sA + BOFF + swzg<CPR>(rb0 + jp * 16, cbk);
                uint32_t rh[4];
                ldmx4(rh, bd);
                const int j0 = jp * 2, j1 = jp * 2 + 1;
#pragma unroll
                for (int t = 0; t < 4; t++) {
                    mma_f16(acc[t][j0], afh[t], rh + 0);
                    mma_f16(acc[t][j1], afh[t], rh + 2);
                }
                if (NPASS == 3) {
                    uint32_t rl[4];
                    ldmx4(rl, bd + TK);
#pragma unroll
                    for (int t = 0; t < 4; t++) {
                        mma_f16(acc[t][j0], afh[t], rl + 0);
                        mma_f16(acc[t][j1], afh[t], rl + 2);
                    }
#pragma unroll
                    for (int t = 0; t < 4; t++) {
                        mma_f16(acc[t][j0], afl[t], rh + 0);
                        mma_f16(acc[t][j1], afl[t], rh + 2);
                    }
                }
            }
        }
        __syncthreads();
    }
#undef ISSUE

    // fp32 epilogue
    const int rbase = warp_m * 64 + (lane >> 2);
    const int cbase = warp_n * 64 + (lane & 3) * 2;
    float* C = O + (size_t)z * batchC;
#pragma unroll
    for (int t = 0; t < 4; t++)
#pragma unroll
        for (int j = 0; j < 8; j++) {
            int rr = m0 + rbase + t * 16;
            int cc = n0 + cbase + j * 8;
            *(float2*)(C + (size_t)rr * ldC + cc) =
                make_float2(acc[t][j][0], acc[t][j][1]);
            *(float2*)(C + (size_t)(rr + 8) * ldC + cc) =
                make_float2(acc[t][j][2], acc[t][j][3]);
        }
}

// ---------------- prep: X split + all-3 weight transpose/split, one launch ---
__global__ void prep_kernel(const float* __restrict__ X,
                            const float* __restrict__ Wq,
                            const float* __restrict__ Wk,
                            const float* __restrict__ Wv,
                            f16* __restrict__ XH, f16* __restrict__ XL,
                            f16* __restrict__ TH, f16* __restrict__ TL,
                            int nx)
{
    int i = blockIdx.x * 256 + threadIdx.x;
    if (i < nx) {
        float x = X[i];
        f16 h = __float2half(x);
        XH[i] = h;
        XL[i] = __float2half(x - __half2float(h));
    } else {
        int j = i - nx;                       // 0 .. 3*DIM*DIM-1
        int w = j / (DIM * DIM);
        int r = j - w * (DIM * DIM);
        int f = r / DIM, d = r - f * DIM;
        const float* W = (w == 0) ? Wq : (w == 1) ? Wk : Wv;
        float x = W[d * DIM + f];
        f16 h = __float2half(x);
        TH[j] = h;
        TL[j] = __float2half(x - __half2float(h));
    }
}

// ---------------- softmax: S fp32 -> P fp16 hi (vectorized) -----------------
__global__ void __launch_bounds__(256)
softmax_kernel(const float* __restrict__ S, f16* __restrict__ Ph)
{
    const int row = blockIdx.x;
    const float4* p4 = (const float4*)(S + (size_t)row * SEQ);
    const int tid = threadIdx.x;

    float4 va = p4[tid];
    float4 vb = p4[tid + 256];
    float m = fmaxf(fmaxf(fmaxf(va.x, va.y), fmaxf(va.z, va.w)),
                    fmaxf(fmaxf(vb.x, vb.y), fmaxf(vb.z, vb.w)));

    __shared__ float red[256];
    red[tid] = m;
    __syncthreads();
#pragma unroll
    for (int s = 128; s > 0; s >>= 1) {
        if (tid < s) red[tid] = fmaxf(red[tid], red[tid + s]);
        __syncthreads();
    }
    m = red[0];
    __syncthreads();

    va.x = expf(va.x - m); va.y = expf(va.y - m);
    va.z = expf(va.z - m); va.w = expf(va.w - m);
    vb.x = expf(vb.x - m); vb.y = expf(vb.y - m);
    vb.z = expf(vb.z - m); vb.w = expf(vb.w - m);
    float sum = (va.x + va.y) + (va.z + va.w) + (vb.x + vb.y) + (vb.z + vb.w);

    red[tid] = sum;
    __syncthreads();
#pragma unroll
    for (int s = 128; s > 0; s >>= 1) {
        if (tid < s) red[tid] += red[tid + s];
        __syncthreads();
    }
    const float inv = 1.0f / red[0];

    __half2* ph2 = (__half2*)(Ph + (size_t)row * SEQ);
#pragma unroll
    for (int half = 0; half < 2; half++) {
        float4 v = half ? vb : va;
        int base = (half ? (tid + 256) : tid) * 2;
        ph2[base + 0] = __halves2half2(__float2half(v.x * inv),
                                       __float2half(v.y * inv));
        ph2[base + 1] = __halves2half2(__float2half(v.z * inv),
                                       __float2half(v.w * inv));
    }
}

// ---------------------------------------------------------------------------
extern "C" void kernel_launch(void* const* d_in, const int* in_sizes, int n_in,
                              void* d_out, int out_size)
{
    const float* X  = (const float*)d_in[0];
    const float* Wq = (const float*)d_in[1];
    const float* Wk = (const float*)d_in[2];
    const float* Wv = (const float*)d_in[3];
    float* out = (float*)d_out;

    f16 *xh, *xl, *wth, *wtl, *qh, *ql, *kh, *kl, *vth, *ph;
    float* s;
    cudaGetSymbolAddress((void**)&xh, g_xh);
    cudaGetSymbolAddress((void**)&xl, g_xl);
    cudaGetSymbolAddress((void**)&wth, g_wth);
    cudaGetSymbolAddress((void**)&wtl, g_wtl);
    cudaGetSymbolAddress((void**)&qh, g_qh);
    cudaGetSymbolAddress((void**)&ql, g_ql);
    cudaGetSymbolAddress((void**)&kh, g_kh);
    cudaGetSymbolAddress((void**)&kl, g_kl);
    cudaGetSymbolAddress((void**)&vth, g_vth);
    cudaGetSymbolAddress((void**)&ph, g_ph);
    cudaGetSymbolAddress((void**)&s, g_s);

    cudaFuncSetAttribute(proj_fused, cudaFuncAttributeMaxDynamicSharedMemorySize, SMEMSZ3);
    cudaFuncSetAttribute(gemm_mma<3, 3, 32>, cudaFuncAttributeMaxDynamicSharedMemorySize, SMEMSZ3);
    cudaFuncSetAttribute(gemm_mma<1, 3, 64>, cudaFuncAttributeMaxDynamicSharedMemorySize, SMEMSZ1);

    const int nx = MTOT * DIM;
    const int ntot = nx + 3 * DIM * DIM;
    prep_kernel<<<(ntot + 255) / 256, 256>>>(X, Wq, Wk, Wv, xh, xl, wth, wtl, nx);

    // Fused QKV projection: grid 18 x 128
    dim3 gp(3 * DIM / 128, MTOT / 128, 1);
    proj_fused<<<gp, 128, SMEMSZ3>>>(xh, xl, wth, wtl, qh, ql, kh, kl, vth);

    // Scores: per batch S = Q * K^T, [2048,2048], K=768 (3-pass, BK=32, 3-stage)
    dim3 gs(SEQ / 128, SEQ / 128, BSZ);
    gemm_mma<3, 3, 32><<<gs, 128, SMEMSZ3>>>(qh, ql, kh, kl, s, DIM,
                                             (long)SEQ * DIM, (long)SEQ * DIM,
                                             (long)SEQ * SEQ, SEQ);

    softmax_kernel<<<BSZ * SEQ, 256>>>(s, ph);

    // Out: per batch O = P * (V^T)^T, [2048,768], K=2048 (1-pass, BK=64, 3-stage)
    dim3 go(DIM / 128, SEQ / 128, BSZ);
    gemm_mma<1, 3, 64><<<go, 128, SMEMSZ1>>>(ph, nullptr, vth, nullptr, out, SEQ,
                                             (long)SEQ * SEQ, (long)DIM * SEQ,
                                             (long)SEQ * DIM, DIM);
}

// round 14
// speedup vs baseline: 1.0181x; 1.0181x over previous
#include <cuda_runtime.h>
#include <cuda_fp16.h>
#include <cstdint>

typedef __half f16;

constexpr int BSZ = 8, SEQ = 2048, DIM = 768;
constexpr int MTOT = BSZ * SEQ;            // 16384

// Swizzled smem tiles: 128 rows x 64B, chunk ^= (row>>1)&3  (16B chunks).
constexpr int TILE  = 8192;
constexpr int STB3  = 4 * TILE;            // 32768: Ah,Al,Bh,Bl
constexpr int STB1  = 2 * TILE;            // 16384: Ah,Bh (PV)
constexpr int SMEMSZ3 = 3 * STB3;          // 98304 (3-stage)
constexpr int SMEMSZ1 = 6 * STB1;          // 98304 (6-stage, PV)
// epi2 staging needs 128*129*4 = 66048 <= both

// ---------------- static device scratch (allocation-free rule) --------------
__device__ f16 g_xh[(size_t)MTOT * DIM];
__device__ f16 g_xl[(size_t)MTOT * DIM];
__device__ f16 g_wth[3][DIM * DIM];        // contiguous [2304 x 768] B^T
__device__ f16 g_wtl[3][DIM * DIM];
__device__ f16 g_qh[(size_t)MTOT * DIM];
__device__ f16 g_ql[(size_t)MTOT * DIM];
__device__ f16 g_kh[(size_t)MTOT * DIM];
__device__ f16 g_kl[(size_t)MTOT * DIM];
__device__ f16 g_vth[(size_t)MTOT * DIM];   // V^T per batch: [b][768][2048], hi only
__device__ float g_s[(size_t)BSZ * SEQ * SEQ];
__device__ f16 g_ph[(size_t)BSZ * SEQ * SEQ];

// ---------------- PTX helpers ----------------------------------------------
__device__ __forceinline__ uint32_t smem_u32(const void* p) {
    uint32_t a;
    asm("{ .reg .u64 t; cvta.to.shared.u64 t, %1; cvt.u32.u64 %0, t; }"
        : "=r"(a) : "l"(p));
    return a;
}

__device__ __forceinline__ void ldmx4(uint32_t* r, uint32_t a) {
    asm volatile("ldmatrix.sync.aligned.m8n8.x4.shared.b16 {%0,%1,%2,%3}, [%4];"
                 : "=r"(r[0]), "=r"(r[1]), "=r"(r[2]), "=r"(r[3]) : "r"(a));
}

__device__ __forceinline__ void mma_f16(float* c, const uint32_t* a, const uint32_t* b) {
    asm volatile(
        "mma.sync.aligned.m16n8k16.row.col.f32.f16.f16.f32 "
        "{%0,%1,%2,%3}, {%4,%5,%6,%7}, {%8,%9}, {%0,%1,%2,%3};"
        : "+f"(c[0]), "+f"(c[1]), "+f"(c[2]), "+f"(c[3])
        : "r"(a[0]), "r"(a[1]), "r"(a[2]), "r"(a[3]), "r"(b[0]), "r"(b[1]));
}

__device__ __forceinline__ void cpasync16(uint32_t s, const void* g) {
    asm volatile("cp.async.cg.shared.global [%0], [%1], 16;" :: "r"(s), "l"(g));
}

// swizzled in-tile offset for (row, 16B-chunk)
__device__ __forceinline__ uint32_t swz(int row, int ch) {
    return (uint32_t)(row * 64 + ((ch ^ ((row >> 1) & 3)) << 4));
}

// ---------------------------------------------------------------------------
// Fused QKV projection.  Grid (18, 128); n0 selects output + pass count:
//   n0 <  768 : Q hi/lo (3-pass)   n0 < 1536 : K hi/lo (3-pass)
//   else      : V^T hi  (2-pass)
// 3-stage cp.async pipeline, swizzled smem.  128 threads, 2 CTAs/SM.
// ---------------------------------------------------------------------------
__global__ void __launch_bounds__(128, 2)
proj_fused(const f16* __restrict__ Ah, const f16* __restrict__ Al,
           const f16* __restrict__ Bh, const f16* __restrict__ Bl,
           f16* __restrict__ Qh, f16* __restrict__ Ql,
           f16* __restrict__ Kh, f16* __restrict__ Kl,
           f16* __restrict__ Vt)
{
    extern __shared__ char smem[];
    const int tid = threadIdx.x, lane = tid & 31, wid = tid >> 5;
    const int m0 = blockIdx.y * 128, n0 = blockIdx.x * 128;
    const int warp_m = wid & 1, warp_n = wid >> 1;
    const bool three = (n0 < 1536);

    const char* pAh = (const char*)Ah;
    const char* pAl = (const char*)Al;
    const char* pBh = (const char*)Bh;
    const char* pBl = (const char*)Bl;

    const uint32_t sb = smem_u32(smem);
    const uint32_t rowbytes = DIM * 2;

    float acc[4][8][4];
#pragma unroll
    for (int t = 0; t < 4; t++)
#pragma unroll
        for (int j = 0; j < 8; j++)
#pragma unroll
            for (int c = 0; c < 4; c++) acc[t][j][c] = 0.0f;

#define PISSUE(kc, buf)                                                          \
    {                                                                            \
        uint32_t s0 = sb + (buf) * STB3;                                         \
        uint32_t kcb = (uint32_t)(kc) * 64;                                      \
        _Pragma("unroll")                                                        \
        for (int i = 0; i < 4; i++) {                                            \
            int c = tid + i * 128;                                               \
            int r = c >> 2, ch = c & 3;                                          \
            size_t goA = (size_t)(m0 + r) * rowbytes + kcb + ch * 16;            \
            size_t goB = (size_t)(n0 + r) * rowbytes + kcb + ch * 16;            \
            uint32_t so = swz(r, ch);                                            \
            cpasync16(s0 + 0 * TILE + so, pAh + goA);                            \
            cpasync16(s0 + 1 * TILE + so, pAl + goA);                            \
            cpasync16(s0 + 2 * TILE + so, pBh + goB);                            \
            if (three) cpasync16(s0 + 3 * TILE + so, pBl + goB);                 \
        }                                                                        \
        asm volatile("cp.async.commit_group;" ::: "memory");                     \
    }

    PISSUE(0, 0);
    PISSUE(1, 1);

    const int nch = DIM >> 5;   // 24
    int cb = 0, ib = 2;
    for (int kc = 0; kc < nch; kc++) {
        asm volatile("cp.async.wait_group 1;" ::: "memory");
        __syncthreads();

        const int knext = kc + 2;
        if (knext < nch) PISSUE(knext, ib);
        ib = (ib + 1 == 3) ? 0 : ib + 1;

        const uint32_t sA = sb + cb * STB3;
        cb = (cb + 1 == 3) ? 0 : cb + 1;

#pragma unroll
        for (int ks = 0; ks < 2; ks++) {
            uint32_t afh[4][4], afl[4][4];

            const int ra0 = warp_m * 64 + (lane & 15);
            const int ca = ks * 2 + (lane >> 4);
#pragma unroll
            for (int t = 0; t < 4; t++) {
                uint32_t ad = sA + swz(ra0 + t * 16, ca);
                ldmx4(afh[t], ad);
                ldmx4(afl[t], ad + TILE);
            }

            const int rb0 = warp_n * 64 + (lane >> 4) * 8 + (lane & 7);
            const int cbk = ks * 2 + ((lane >> 3) & 1);
#pragma unroll
            for (int jp = 0; jp < 4; jp++) {
                uint32_t bd = sA + 2 * TILE + swz(rb0 + jp * 16, cbk);
                uint32_t rh[4];
                ldmx4(rh, bd);
                const int j0 = jp * 2, j1 = jp * 2 + 1;
#pragma unroll
                for (int t = 0; t < 4; t++) {
                    mma_f16(acc[t][j0], afh[t], rh + 0);
                    mma_f16(acc[t][j1], afh[t], rh + 2);
                }
                if (three) {
                    uint32_t rl[4];
                    ldmx4(rl, bd + TILE);
#pragma unroll
                    for (int t = 0; t < 4; t++) {
                        mma_f16(acc[t][j0], afh[t], rl + 0);
                        mma_f16(acc[t][j1], afh[t], rl + 2);
                    }
                }
#pragma unroll
                for (int t = 0; t < 4; t++) {
                    mma_f16(acc[t][j0], afl[t], rh + 0);
                    mma_f16(acc[t][j1], afl[t], rh + 2);
                }
            }
        }
        __syncthreads();
    }
#undef PISSUE

    // ---------------- epilogue dispatch ----------------
    const int rbase = warp_m * 64 + (lane >> 2);
    const int cbase = warp_n * 64 + (lane & 3) * 2;

    if (three) {
        f16* Oh = (n0 < 768) ? Qh : Kh;
        f16* Ol = (n0 < 768) ? Ql : Kl;
        const int nc0 = (n0 < 768) ? n0 : n0 - 768;
#pragma unroll
        for (int t = 0; t < 4; t++)
#pragma unroll
            for (int j = 0; j < 8; j++)
#pragma unroll
                for (int h = 0; h < 2; h++) {
                    int rr = m0 + rbase + t * 16 + h * 8;
                    int cc = nc0 + cbase + j * 8;
                    float x0 = acc[t][j][h * 2 + 0], x1 = acc[t][j][h * 2 + 1];
                    f16 h0 = __float2half(x0), h1 = __float2half(x1);
                    f16 l0 = __float2half(x0 - __half2float(h0));
                    f16 l1 = __float2half(x1 - __half2float(h1));
                    *(__half2*)(Oh + (size_t)rr * DIM + cc) = __halves2half2(h0, h1);
                    *(__half2*)(Ol + (size_t)rr * DIM + cc) = __halves2half2(l0, l1);
                }
    } else {
        float* st = (float*)smem;
#pragma unroll
        for (int t = 0; t < 4; t++)
#pragma unroll
            for (int j = 0; j < 8; j++)
#pragma unroll
                for (int h = 0; h < 2; h++) {
                    int rr = rbase + t * 16 + h * 8;
                    int cc = cbase + j * 8;
                    st[(size_t)rr * 129 + cc + 0] = acc[t][j][h * 2 + 0];
                    st[(size_t)rr * 129 + cc + 1] = acc[t][j][h * 2 + 1];
                }
        __syncthreads();
        const int nv0 = n0 - 1536;
        for (int idx = tid; idx < 128 * 128; idx += 128) {
            int nl = idx >> 7, ml = idx & 127;
            int mg = m0 + ml;
            int b = mg >> 11, mloc = mg & 2047;
            float x = st[(size_t)ml * 129 + nl];
            size_t o = (size_t)b * DIM * SEQ + (size_t)(nv0 + nl) * SEQ + mloc;
            Vt[o] = __float2half(x);
        }
    }
}

// ---------------------------------------------------------------------------
// Batched GEMM: NPASS=3 (scores, 3-stage) / NPASS=1 (PV, 6-stage), fp32 out.
// 128 threads, tile 128x128, warp tile 64x64, 2 CTAs/SM, BK=32.
// ---------------------------------------------------------------------------
template <int NPASS, int NSTAGE>
__global__ void __launch_bounds__(128, 2)
gemm_mma(const f16* __restrict__ Ah, const f16* __restrict__ Al,
         const f16* __restrict__ Bh, const f16* __restrict__ Bl,
         float* __restrict__ O,
         int K, long batchA, long batchB, long batchC, int ldC)
{
    constexpr int STB  = (NPASS == 1) ? STB1 : STB3;
    constexpr int BOFF = (NPASS == 1) ? TILE : 2 * TILE;   // B_HI offset

    extern __shared__ char smem[];
    const int tid = threadIdx.x, lane = tid & 31, wid = tid >> 5;
    const int z = blockIdx.z;
    const int m0 = blockIdx.y * 128, n0 = blockIdx.x * 128;
    const int warp_m = wid & 1, warp_n = wid >> 1;

    const char* pAh = (const char*)(Ah + (size_t)z * batchA);
    const char* pAl = (NPASS == 3) ? (const char*)(Al + (size_t)z * batchA) : nullptr;
    const char* pBh = (const char*)(Bh + (size_t)z * batchB);
    const char* pBl = (NPASS == 3) ? (const char*)(Bl + (size_t)z * batchB) : nullptr;

    const uint32_t sb = smem_u32(smem);
    const uint32_t rowbytes = (uint32_t)K * 2;

    float acc[4][8][4];
#pragma unroll
    for (int t = 0; t < 4; t++)
#pragma unroll
        for (int j = 0; j < 8; j++)
#pragma unroll
            for (int c = 0; c < 4; c++) acc[t][j][c] = 0.0f;

    const int nch = K >> 5;

#define ISSUE(kc, buf)                                                           \
    {                                                                            \
        uint32_t s0 = sb + (buf) * STB;                                          \
        uint32_t kcb = (uint32_t)(kc) * 64;                                      \
        _Pragma("unroll")                                                        \
        for (int i = 0; i < 4; i++) {                                            \
            int c = tid + i * 128;                                               \
            int r = c >> 2, ch = c & 3;                                          \
            size_t goA = (size_t)(m0 + r) * rowbytes + kcb + ch * 16;            \
            size_t goB = (size_t)(n0 + r) * rowbytes + kcb + ch * 16;            \
            uint32_t so = swz(r, ch);                                            \
            cpasync16(s0 + so, pAh + goA);                                       \
            if (NPASS == 3) cpasync16(s0 + TILE + so, pAl + goA);                \
            cpasync16(s0 + BOFF + so, pBh + goB);                                \
            if (NPASS == 3) cpasync16(s0 + 3 * TILE + so, pBl + goB);            \
        }                                                                        \
        asm volatile("cp.async.commit_group;" ::: "memory");                     \
    }

#pragma unroll
    for (int p = 0; p < NSTAGE - 1; p++) ISSUE(p, p);

    int cb = 0, ib = NSTAGE - 1;
    for (int kc = 0; kc < nch; kc++) {
        asm volatile("cp.async.wait_group %0;" :: "n"(NSTAGE - 2) : "memory");
        __syncthreads();

        const int knext = kc + NSTAGE - 1;
        if (knext < nch) ISSUE(knext, ib);
        ib = (ib + 1 == NSTAGE) ? 0 : ib + 1;

        const uint32_t sA = sb + cb * STB;
        cb = (cb + 1 == NSTAGE) ? 0 : cb + 1;

#pragma unroll
        for (int ks = 0; ks < 2; ks++) {
            uint32_t afh[4][4], afl[4][4];

            const int ra0 = warp_m * 64 + (lane & 15);
            const int ca = ks * 2 + (lane >> 4);
#pragma unroll
            for (int t = 0; t < 4; t++) {
                uint32_t ad = sA + swz(ra0 + t * 16, ca);
                ldmx4(afh[t], ad);
                if (NPASS == 3) ldmx4(afl[t], ad + TILE);
            }

            const int rb0 = warp_n * 64 + (lane >> 4) * 8 + (lane & 7);
            const int cbk = ks * 2 + ((lane >> 3) & 1);
#pragma unroll
            for (int jp = 0; jp < 4; jp++) {
                uint32_t bd = sA + BOFF + swz(rb0 + jp * 16, cbk);
                uint32_t rh[4];
                ldmx4(rh, bd);
                const int j0 = jp * 2, j1 = jp * 2 + 1;
#pragma unroll
                for (int t = 0; t < 4; t++) {
                    mma_f16(acc[t][j0], afh[t], rh + 0);
                    mma_f16(acc[t][j1], afh[t], rh + 2);
                }
                if (NPASS == 3) {
                    uint32_t rl[4];
                    ldmx4(rl, bd + TILE);
#pragma unroll
                    for (int t = 0; t < 4; t++) {
                        mma_f16(acc[t][j0], afh[t], rl + 0);
                        mma_f16(acc[t][j1], afh[t], rl + 2);
                    }
#pragma unroll
                    for (int t = 0; t < 4; t++) {
                        mma_f16(acc[t][j0], afl[t], rh + 0);
                        mma_f16(acc[t][j1], afl[t], rh + 2);
                    }
                }
            }
        }
        __syncthreads();
    }
#undef ISSUE

    // fp32 epilogue
    const int rbase = warp_m * 64 + (lane >> 2);
    const int cbase = warp_n * 64 + (lane & 3) * 2;
    float* C = O + (size_t)z * batchC;
#pragma unroll
    for (int t = 0; t < 4; t++)
#pragma unroll
        for (int j = 0; j < 8; j++) {
            int rr = m0 + rbase + t * 16;
            int cc = n0 + cbase + j * 8;
            *(float2*)(C + (size_t)rr * ldC + cc) =
                make_float2(acc[t][j][0], acc[t][j][1]);
            *(float2*)(C + (size_t)(rr + 8) * ldC + cc) =
                make_float2(acc[t][j][2], acc[t][j][3]);
        }
}

// ---------------- prep: X split + all-3 weight transpose/split, one launch ---
__global__ void prep_kernel(const float* __restrict__ X,
                            const float* __restrict__ Wq,
                            const float* __restrict__ Wk,
                            const float* __restrict__ Wv,
                            f16* __restrict__ XH, f16* __restrict__ XL,
                            f16* __restrict__ TH, f16* __restrict__ TL,
                            int nx)
{
    int i = blockIdx.x * 256 + threadIdx.x;
    if (i < nx) {
        float x = X[i];
        f16 h = __float2half(x);
        XH[i] = h;
        XL[i] = __float2half(x - __half2float(h));
    } else {
        int j = i - nx;                       // 0 .. 3*DIM*DIM-1
        int w = j / (DIM * DIM);
        int r = j - w * (DIM * DIM);
        int f = r / DIM, d = r - f * DIM;
        const float* W = (w == 0) ? Wq : (w == 1) ? Wk : Wv;
        float x = W[d * DIM + f];
        f16 h = __float2half(x);
        TH[j] = h;
        TL[j] = __float2half(x - __half2float(h));
    }
}

// ---------------- softmax: shuffle reductions + __expf, streaming -----------
__global__ void __launch_bounds__(256)
softmax_kernel(const float* __restrict__ S, f16* __restrict__ Ph)
{
    const int row = blockIdx.x;
    const float4* p4 = (const float4*)(S + (size_t)row * SEQ);
    const int tid = threadIdx.x;
    const int lane = tid & 31, wid = tid >> 5;

    float4 va = p4[tid];
    float4 vb = p4[tid + 256];
    float m = fmaxf(fmaxf(fmaxf(va.x, va.y), fmaxf(va.z, va.w)),
                    fmaxf(fmaxf(vb.x, vb.y), fmaxf(vb.z, vb.w)));

    // warp max
#pragma unroll
    for (int o = 16; o > 0; o >>= 1)
        m = fmaxf(m, __shfl_xor_sync(0xFFFFFFFF, m, o));

    __shared__ float red[8];
    if (lane == 0) red[wid] = m;
    __syncthreads();
    if (wid == 0) {
        float w = (lane < 8) ? red[lane] : -1e30f;
#pragma unroll
        for (int o = 4; o > 0; o >>= 1)
            w = fmaxf(w, __shfl_xor_sync(0xFFFFFFFF, w, o));
        if (lane == 0) red[0] = w;
    }
    __syncthreads();
    m = red[0];

    va.x = __expf(va.x - m); va.y = __expf(va.y - m);
    va.z = __expf(va.z - m); va.w = __expf(va.w - m);
    vb.x = __expf(vb.x - m); vb.y = __expf(vb.y - m);
    vb.z = __expf(vb.z - m); vb.w = __expf(vb.w - m);
    float sum = (va.x + va.y) + (va.z + va.w) + (vb.x + vb.y) + (vb.z + vb.w);

    // warp sum
#pragma unroll
    for (int o = 16; o > 0; o >>= 1)
        sum += __shfl_xor_sync(0xFFFFFFFF, sum, o);

    __shared__ float red2[8];
    if (lane == 0) red2[wid] = sum;
    __syncthreads();
    if (wid == 0) {
        float w = (lane < 8) ? red2[lane] : 0.0f;
#pragma unroll
        for (int o = 4; o > 0; o >>= 1)
            w += __shfl_xor_sync(0xFFFFFFFF, w, o);
        if (lane == 0) red2[0] = w;
    }
    __syncthreads();
    const float inv = 1.0f / red2[0];

    __half2* ph2 = (__half2*)(Ph + (size_t)row * SEQ);
#pragma unroll
    for (int half = 0; half < 2; half++) {
        float4 v = half ? vb : va;
        int base = (half ? (tid + 256) : tid) * 2;
        ph2[base + 0] = __halves2half2(__float2half(v.x * inv),
                                       __float2half(v.y * inv));
        ph2[base + 1] = __halves2half2(__float2half(v.z * inv),
                                       __float2half(v.w * inv));
    }
}

// ---------------------------------------------------------------------------
extern "C" void kernel_launch(void* const* d_in, const int* in_sizes, int n_in,
                              void* d_out, int out_size)
{
    const float* X  = (const float*)d_in[0];
    const float* Wq = (const float*)d_in[1];
    const float* Wk = (const float*)d_in[2];
    const float* Wv = (const float*)d_in[3];
    float* out = (float*)d_out;

    f16 *xh, *xl, *wth, *wtl, *qh, *ql, *kh, *kl, *vth, *ph;
    float* s;
    cudaGetSymbolAddress((void**)&xh, g_xh);
    cudaGetSymbolAddress((void**)&xl, g_xl);
    cudaGetSymbolAddress((void**)&wth, g_wth);
    cudaGetSymbolAddress((void**)&wtl, g_wtl);
    cudaGetSymbolAddress((void**)&qh, g_qh);
    cudaGetSymbolAddress((void**)&ql, g_ql);
    cudaGetSymbolAddress((void**)&kh, g_kh);
    cudaGetSymbolAddress((void**)&kl, g_kl);
    cudaGetSymbolAddress((void**)&vth, g_vth);
    cudaGetSymbolAddress((void**)&ph, g_ph);
    cudaGetSymbolAddress((void**)&s, g_s);

    cudaFuncSetAttribute(proj_fused, cudaFuncAttributeMaxDynamicSharedMemorySize, SMEMSZ3);
    cudaFuncSetAttribute(gemm_mma<3, 3>, cudaFuncAttributeMaxDynamicSharedMemorySize, SMEMSZ3);
    cudaFuncSetAttribute(gemm_mma<1, 6>, cudaFuncAttributeMaxDynamicSharedMemorySize, SMEMSZ1);

    const int nx = MTOT * DIM;
    const int ntot = nx + 3 * DIM * DIM;
    prep_kernel<<<(ntot + 255) / 256, 256>>>(X, Wq, Wk, Wv, xh, xl, wth, wtl, nx);

    // Fused QKV projection: grid 18 x 128
    dim3 gp(3 * DIM / 128, MTOT / 128, 1);
    proj_fused<<<gp, 128, SMEMSZ3>>>(xh, xl, wth, wtl, qh, ql, kh, kl, vth);

    // Scores: per batch S = Q * K^T, [2048,2048], K=768 (3-pass, 3-stage)
    dim3 gs(SEQ / 128, SEQ / 128, BSZ);
    gemm_mma<3, 3><<<gs, 128, SMEMSZ3>>>(qh, ql, kh, kl, s, DIM,
                                         (long)SEQ * DIM, (long)SEQ * DIM,
                                         (long)SEQ * SEQ, SEQ);

    softmax_kernel<<<BSZ * SEQ, 256>>>(s, ph);

    // Out: per batch O = P * (V^T)^T, [2048,768], K=2048 (1-pass, 6-stage)
    dim3 go(DIM / 128, SEQ / 128, BSZ);
    gemm_mma<1, 6><<<go, 128, SMEMSZ1>>>(ph, nullptr, vth, nullptr, out, SEQ,
                                         (long)SEQ * SEQ, (long)DIM * SEQ,
                                         (long)SEQ * DIM, DIM);
}

// round 15
// speedup vs baseline: 1.0290x; 1.0107x over previous
#include <cuda_runtime.h>
#include <cuda_fp16.h>
#include <cstdint>

typedef __half f16;

constexpr int BSZ = 8, SEQ = 2048, DIM = 768;
constexpr int MTOT = BSZ * SEQ;            // 16384

// Swizzled smem tiles: 128 rows x 64B, chunk ^= (row>>1)&3  (16B chunks).
constexpr int TILE  = 8192;
constexpr int STB3  = 4 * TILE;            // 32768: Ah,Al,Bh,Bl
constexpr int STB1  = 2 * TILE;            // 16384: Ah,Bh (PV)
constexpr int SMEMSZ3 = 3 * STB3;          // 98304 (3-stage)
constexpr int SMEMSZ1 = 6 * STB1;          // 98304 (6-stage, PV)
// epi2 staging needs 128*129*4 = 66048 <= both

// ---------------- static device scratch (allocation-free rule) --------------
__device__ f16 g_xh[(size_t)MTOT * DIM];
__device__ f16 g_xl[(size_t)MTOT * DIM];
__device__ f16 g_wth[3][DIM * DIM];        // contiguous [2304 x 768] B^T
__device__ f16 g_wtl[3][DIM * DIM];
__device__ f16 g_qh[(size_t)MTOT * DIM];
__device__ f16 g_ql[(size_t)MTOT * DIM];
__device__ f16 g_kh[(size_t)MTOT * DIM];
__device__ f16 g_kl[(size_t)MTOT * DIM];
__device__ f16 g_vth[(size_t)MTOT * DIM];   // V^T per batch: [b][768][2048], hi only
__device__ float g_s[(size_t)BSZ * SEQ * SEQ];
__device__ f16 g_ph[(size_t)BSZ * SEQ * SEQ];

// ---------------- PTX helpers ----------------------------------------------
__device__ __forceinline__ uint32_t smem_u32(const void* p) {
    uint32_t a;
    asm("{ .reg .u64 t; cvta.to.shared.u64 t, %1; cvt.u32.u64 %0, t; }"
        : "=r"(a) : "l"(p));
    return a;
}

__device__ __forceinline__ void ldmx4(uint32_t* r, uint32_t a) {
    asm volatile("ldmatrix.sync.aligned.m8n8.x4.shared.b16 {%0,%1,%2,%3}, [%4];"
                 : "=r"(r[0]), "=r"(r[1]), "=r"(r[2]), "=r"(r[3]) : "r"(a));
}

__device__ __forceinline__ void mma_f16(float* c, const uint32_t* a, const uint32_t* b) {
    asm volatile(
        "mma.sync.aligned.m16n8k16.row.col.f32.f16.f16.f32 "
        "{%0,%1,%2,%3}, {%4,%5,%6,%7}, {%8,%9}, {%0,%1,%2,%3};"
        : "+f"(c[0]), "+f"(c[1]), "+f"(c[2]), "+f"(c[3])
        : "r"(a[0]), "r"(a[1]), "r"(a[2]), "r"(a[3]), "r"(b[0]), "r"(b[1]));
}

__device__ __forceinline__ void cpasync16(uint32_t s, const void* g) {
    asm volatile("cp.async.cg.shared.global [%0], [%1], 16;" :: "r"(s), "l"(g));
}

// swizzled in-tile offset for (row, 16B-chunk)
__device__ __forceinline__ uint32_t swz(int row, int ch) {
    return (uint32_t)(row * 64 + ((ch ^ ((row >> 1) & 3)) << 4));
}

// ---------------------------------------------------------------------------
// Fused QKV projection.  Grid (18, 128); n0 selects output + pass count:
//   n0 <  768 : Q hi/lo (3-pass)   n0 < 1536 : K hi/lo (3-pass)
//   else      : V^T hi  (2-pass)
// 3-stage cp.async pipeline, swizzled smem.  128 threads, 2 CTAs/SM.
// ---------------------------------------------------------------------------
__global__ void __launch_bounds__(128, 2)
proj_fused(const f16* __restrict__ Ah, const f16* __restrict__ Al,
           const f16* __restrict__ Bh, const f16* __restrict__ Bl,
           f16* __restrict__ Qh, f16* __restrict__ Ql,
           f16* __restrict__ Kh, f16* __restrict__ Kl,
           f16* __restrict__ Vt)
{
    extern __shared__ char smem[];
    const int tid = threadIdx.x, lane = tid & 31, wid = tid >> 5;
    const int m0 = blockIdx.y * 128, n0 = blockIdx.x * 128;
    const int warp_m = wid & 1, warp_n = wid >> 1;
    const bool three = (n0 < 1536);

    const char* pAh = (const char*)Ah;
    const char* pAl = (const char*)Al;
    const char* pBh = (const char*)Bh;
    const char* pBl = (const char*)Bl;

    const uint32_t sb = smem_u32(smem);
    const uint32_t rowbytes = DIM * 2;

    float acc[4][8][4];
#pragma unroll
    for (int t = 0; t < 4; t++)
#pragma unroll
        for (int j = 0; j < 8; j++)
#pragma unroll
            for (int c = 0; c < 4; c++) acc[t][j][c] = 0.0f;

#define PISSUE(kc, buf)                                                          \
    {                                                                            \
        uint32_t s0 = sb + (buf) * STB3;                                         \
        uint32_t kcb = (uint32_t)(kc) * 64;                                      \
        _Pragma("unroll")                                                        \
        for (int i = 0; i < 4; i++) {                                            \
            int c = tid + i * 128;                                               \
            int r = c >> 2, ch = c & 3;                                          \
            size_t goA = (size_t)(m0 + r) * rowbytes + kcb + ch * 16;            \
            size_t goB = (size_t)(n0 + r) * rowbytes + kcb + ch * 16;            \
            uint32_t so = swz(r, ch);                                            \
            cpasync16(s0 + 0 * TILE + so, pAh + goA);                            \
            cpasync16(s0 + 1 * TILE + so, pAl + goA);                            \
            cpasync16(s0 + 2 * TILE + so, pBh + goB);                            \
            if (three) cpasync16(s0 + 3 * TILE + so, pBl + goB);                 \
        }                                                                        \
        asm volatile("cp.async.commit_group;" ::: "memory");                     \
    }

    PISSUE(0, 0);
    PISSUE(1, 1);

    const int nch = DIM >> 5;   // 24
    int cb = 0, ib = 2;
    for (int kc = 0; kc < nch; kc++) {
        asm volatile("cp.async.wait_group 1;" ::: "memory");
        __syncthreads();

        const int knext = kc + 2;
        if (knext < nch) PISSUE(knext, ib);
        ib = (ib + 1 == 3) ? 0 : ib + 1;

        const uint32_t sA = sb + cb * STB3;
        cb = (cb + 1 == 3) ? 0 : cb + 1;

#pragma unroll
        for (int ks = 0; ks < 2; ks++) {
            uint32_t afh[4][4], afl[4][4];

            const int ra0 = warp_m * 64 + (lane & 15);
            const int ca = ks * 2 + (lane >> 4);
#pragma unroll
            for (int t = 0; t < 4; t++) {
                uint32_t ad = sA + swz(ra0 + t * 16, ca);
                ldmx4(afh[t], ad);
                ldmx4(afl[t], ad + TILE);
            }

            const int rb0 = warp_n * 64 + (lane >> 4) * 8 + (lane & 7);
            const int cbk = ks * 2 + ((lane >> 3) & 1);
#pragma unroll
            for (int jp = 0; jp < 4; jp++) {
                uint32_t bd = sA + 2 * TILE + swz(rb0 + jp * 16, cbk);
                uint32_t rh[4];
                ldmx4(rh, bd);
                const int j0 = jp * 2, j1 = jp * 2 + 1;
#pragma unroll
                for (int t = 0; t < 4; t++) {
                    mma_f16(acc[t][j0], afh[t], rh + 0);
                    mma_f16(acc[t][j1], afh[t], rh + 2);
                }
                if (three) {
                    uint32_t rl[4];
                    ldmx4(rl, bd + TILE);
#pragma unroll
                    for (int t = 0; t < 4; t++) {
                        mma_f16(acc[t][j0], afh[t], rl + 0);
                        mma_f16(acc[t][j1], afh[t], rl + 2);
                    }
                }
#pragma unroll
                for (int t = 0; t < 4; t++) {
                    mma_f16(acc[t][j0], afl[t], rh + 0);
                    mma_f16(acc[t][j1], afl[t], rh + 2);
                }
            }
        }
        __syncthreads();
    }
#undef PISSUE

    // ---------------- epilogue dispatch ----------------
    const int rbase = warp_m * 64 + (lane >> 2);
    const int cbase = warp_n * 64 + (lane & 3) * 2;

    if (three) {
        f16* Oh = (n0 < 768) ? Qh : Kh;
        f16* Ol = (n0 < 768) ? Ql : Kl;
        const int nc0 = (n0 < 768) ? n0 : n0 - 768;
#pragma unroll
        for (int t = 0; t < 4; t++)
#pragma unroll
            for (int j = 0; j < 8; j++)
#pragma unroll
                for (int h = 0; h < 2; h++) {
                    int rr = m0 + rbase + t * 16 + h * 8;
                    int cc = nc0 + cbase + j * 8;
                    float x0 = acc[t][j][h * 2 + 0], x1 = acc[t][j][h * 2 + 1];
                    f16 h0 = __float2half(x0), h1 = __float2half(x1);
                    f16 l0 = __float2half(x0 - __half2float(h0));
                    f16 l1 = __float2half(x1 - __half2float(h1));
                    *(__half2*)(Oh + (size_t)rr * DIM + cc) = __halves2half2(h0, h1);
                    *(__half2*)(Ol + (size_t)rr * DIM + cc) = __halves2half2(l0, l1);
                }
    } else {
        float* st = (float*)smem;
#pragma unroll
        for (int t = 0; t < 4; t++)
#pragma unroll
            for (int j = 0; j < 8; j++)
#pragma unroll
                for (int h = 0; h < 2; h++) {
                    int rr = rbase + t * 16 + h * 8;
                    int cc = cbase + j * 8;
                    st[(size_t)rr * 129 + cc + 0] = acc[t][j][h * 2 + 0];
                    st[(size_t)rr * 129 + cc + 1] = acc[t][j][h * 2 + 1];
                }
        __syncthreads();
        const int nv0 = n0 - 1536;
        for (int idx = tid; idx < 128 * 128; idx += 128) {
            int nl = idx >> 7, ml = idx & 127;
            int mg = m0 + ml;
            int b = mg >> 11, mloc = mg & 2047;
            float x = st[(size_t)ml * 129 + nl];
            size_t o = (size_t)b * DIM * SEQ + (size_t)(nv0 + nl) * SEQ + mloc;
            Vt[o] = __float2half(x);
        }
    }
}

// ---------------------------------------------------------------------------
// Batched GEMM: NPASS=3 (scores, 3-stage) / NPASS=1 (PV, 6-stage), fp32 out.
// 128 threads, tile 128x128, warp tile 64x64, 2 CTAs/SM, BK=32.
// ---------------------------------------------------------------------------
template <int NPASS, int NSTAGE>
__global__ void __launch_bounds__(128, 2)
gemm_mma(const f16* __restrict__ Ah, const f16* __restrict__ Al,
         const f16* __restrict__ Bh, const f16* __restrict__ Bl,
         float* __restrict__ O,
         int K, long batchA, long batchB, long batchC, int ldC)
{
    constexpr int STB  = (NPASS == 1) ? STB1 : STB3;
    constexpr int BOFF = (NPASS == 1) ? TILE : 2 * TILE;   // B_HI offset

    extern __shared__ char smem[];
    const int tid = threadIdx.x, lane = tid & 31, wid = tid >> 5;
    const int z = blockIdx.z;
    const int m0 = blockIdx.y * 128, n0 = blockIdx.x * 128;
    const int warp_m = wid & 1, warp_n = wid >> 1;

    const char* pAh = (const char*)(Ah + (size_t)z * batchA);
    const char* pAl = (NPASS == 3) ? (const char*)(Al + (size_t)z * batchA) : nullptr;
    const char* pBh = (const char*)(Bh + (size_t)z * batchB);
    const char* pBl = (NPASS == 3) ? (const char*)(Bl + (size_t)z * batchB) : nullptr;

    const uint32_t sb = smem_u32(smem);
    const uint32_t rowbytes = (uint32_t)K * 2;

    float acc[4][8][4];
#pragma unroll
    for (int t = 0; t < 4; t++)
#pragma unroll
        for (int j = 0; j < 8; j++)
#pragma unroll
            for (int c = 0; c < 4; c++) acc[t][j][c] = 0.0f;

    const int nch = K >> 5;

#define ISSUE(kc, buf)                                                           \
    {                                                                            \
        uint32_t s0 = sb + (buf) * STB;                                          \
        uint32_t kcb = (uint32_t)(kc) * 64;                                      \
        _Pragma("unroll")                                                        \
        for (int i = 0; i < 4; i++) {                                            \
            int c = tid + i * 128;                                               \
            int r = c >> 2, ch = c & 3;                                          \
            size_t goA = (size_t)(m0 + r) * rowbytes + kcb + ch * 16;            \
            size_t goB = (size_t)(n0 + r) * rowbytes + kcb + ch * 16;            \
            uint32_t so = swz(r, ch);                                            \
            cpasync16(s0 + so, pAh + goA);                                       \
            if (NPASS == 3) cpasync16(s0 + TILE + so, pAl + goA);                \
            cpasync16(s0 + BOFF + so, pBh + goB);                                \
            if (NPASS == 3) cpasync16(s0 + 3 * TILE + so, pBl + goB);            \
        }                                                                        \
        asm volatile("cp.async.commit_group;" ::: "memory");                     \
    }

#pragma unroll
    for (int p = 0; p < NSTAGE - 1; p++) ISSUE(p, p);

    int cb = 0, ib = NSTAGE - 1;
    for (int kc = 0; kc < nch; kc++) {
        asm volatile("cp.async.wait_group %0;" :: "n"(NSTAGE - 2) : "memory");
        __syncthreads();

        const int knext = kc + NSTAGE - 1;
        if (knext < nch) ISSUE(knext, ib);
        ib = (ib + 1 == NSTAGE) ? 0 : ib + 1;

        const uint32_t sA = sb + cb * STB;
        cb = (cb + 1 == NSTAGE) ? 0 : cb + 1;

#pragma unroll
        for (int ks = 0; ks < 2; ks++) {
            uint32_t afh[4][4], afl[4][4];

            const int ra0 = warp_m * 64 + (lane & 15);
            const int ca = ks * 2 + (lane >> 4);
#pragma unroll
            for (int t = 0; t < 4; t++) {
                uint32_t ad = sA + swz(ra0 + t * 16, ca);
                ldmx4(afh[t], ad);
                if (NPASS == 3) ldmx4(afl[t], ad + TILE);
            }

            const int rb0 = warp_n * 64 + (lane >> 4) * 8 + (lane & 7);
            const int cbk = ks * 2 + ((lane >> 3) & 1);
#pragma unroll
            for (int jp = 0; jp < 4; jp++) {
                uint32_t bd = sA + BOFF + swz(rb0 + jp * 16, cbk);
                uint32_t rh[4];
                ldmx4(rh, bd);
                const int j0 = jp * 2, j1 = jp * 2 + 1;
#pragma unroll
                for (int t = 0; t < 4; t++) {
                    mma_f16(acc[t][j0], afh[t], rh + 0);
                    mma_f16(acc[t][j1], afh[t], rh + 2);
                }
                if (NPASS == 3) {
                    uint32_t rl[4];
                    ldmx4(rl, bd + TILE);
#pragma unroll
                    for (int t = 0; t < 4; t++) {
                        mma_f16(acc[t][j0], afh[t], rl + 0);
                        mma_f16(acc[t][j1], afh[t], rl + 2);
                    }
#pragma unroll
                    for (int t = 0; t < 4; t++) {
                        mma_f16(acc[t][j0], afl[t], rh + 0);
                        mma_f16(acc[t][j1], afl[t], rh + 2);
                    }
                }
            }
        }
        __syncthreads();
    }
#undef ISSUE

    // fp32 epilogue
    const int rbase = warp_m * 64 + (lane >> 2);
    const int cbase = warp_n * 64 + (lane & 3) * 2;
    float* C = O + (size_t)z * batchC;
#pragma unroll
    for (int t = 0; t < 4; t++)
#pragma unroll
        for (int j = 0; j < 8; j++) {
            int rr = m0 + rbase + t * 16;
            int cc = n0 + cbase + j * 8;
            *(float2*)(C + (size_t)rr * ldC + cc) =
                make_float2(acc[t][j][0], acc[t][j][1]);
            *(float2*)(C + (size_t)(rr + 8) * ldC + cc) =
                make_float2(acc[t][j][2], acc[t][j][3]);
        }
}

// ---------------- prep: X hi/lo split (coalesced) ---------------------------
__global__ void xsplit_kernel(const float* __restrict__ X,
                              f16* __restrict__ H, f16* __restrict__ L, int n)
{
    int i = blockIdx.x * 256 + threadIdx.x;
    if (i < n) {
        float x = X[i];
        f16 h = __float2half(x);
        H[i] = h;
        L[i] = __float2half(x - __half2float(h));
    }
}

// ---------------- prep: tiled weight transpose + split (coalesced) ----------
// Grid (24, 24, 3), block (32, 8).  Reads W coalesced along f, writes W^T
// coalesced along d via a 32x33 smem tile.
__global__ void wtrans_kernel(const float* __restrict__ Wq,
                              const float* __restrict__ Wk,
                              const float* __restrict__ Wv,
                              f16* __restrict__ TH, f16* __restrict__ TL)
{
    __shared__ float t[32][33];
    const int w = blockIdx.z;
    const float* W = (w == 0) ? Wq : (w == 1) ? Wk : Wv;
    f16* th = TH + (size_t)w * DIM * DIM;
    f16* tl = TL + (size_t)w * DIM * DIM;

    const int f0 = blockIdx.x * 32;   // column block in W (= row block in W^T)
    const int d0 = blockIdx.y * 32;   // row block in W    (= col block in W^T)
    const int tx = threadIdx.x, ty = threadIdx.y;

#pragma unroll
    for (int i = 0; i < 4; i++) {
        int d = d0 + ty + i * 8;
        t[ty + i * 8][tx] = W[(size_t)d * DIM + f0 + tx];   // coalesced in f
    }
    __syncthreads();

#pragma unroll
    for (int i = 0; i < 4; i++) {
        int f = f0 + ty + i * 8;
        float x = t[tx][ty + i * 8];                        // transposed read
        f16 h = __float2half(x);
        size_t o = (size_t)f * DIM + d0 + tx;               // coalesced in d
        th[o] = h;
        tl[o] = __float2half(x - __half2float(h));
    }
}

// ---------------- softmax: 2 rows/CTA, shuffle reduce, __expf ---------------
__global__ void __launch_bounds__(256)
softmax_kernel(const float* __restrict__ S, f16* __restrict__ Ph)
{
    const int tid = threadIdx.x;
    const int half = tid >> 7;                 // which row of the pair
    const int tr = tid & 127;                  // thread-in-row
    const int lane = tid & 31;
    const int wir = (tid >> 5) & 3;            // warp-in-row
    const int row = blockIdx.x * 2 + half;

    const float4* p4 = (const float4*)(S + (size_t)row * SEQ);
    float4 v[4];
    float m = -1e30f;
#pragma unroll
    for (int k = 0; k < 4; k++) {
        v[k] = p4[tr + k * 128];
        m = fmaxf(m, fmaxf(fmaxf(v[k].x, v[k].y), fmaxf(v[k].z, v[k].w)));
    }
#pragma unroll
    for (int o = 16; o > 0; o >>= 1)
        m = fmaxf(m, __shfl_xor_sync(0xFFFFFFFF, m, o));

    __shared__ float redm[2][4];
    if (lane == 0) redm[half][wir] = m;
    __syncthreads();
    m = fmaxf(fmaxf(redm[half][0], redm[half][1]),
              fmaxf(redm[half][2], redm[half][3]));

    float sum = 0.0f;
#pragma unroll
    for (int k = 0; k < 4; k++) {
        v[k].x = __expf(v[k].x - m); v[k].y = __expf(v[k].y - m);
        v[k].z = __expf(v[k].z - m); v[k].w = __expf(v[k].w - m);
        sum += (v[k].x + v[k].y) + (v[k].z + v[k].w);
    }
#pragma unroll
    for (int o = 16; o > 0; o >>= 1)
        sum += __shfl_xor_sync(0xFFFFFFFF, sum, o);

    __shared__ float reds[2][4];
    if (lane == 0) reds[half][wir] = sum;
    __syncthreads();
    const float inv = 1.0f / ((reds[half][0] + reds[half][1]) +
                              (reds[half][2] + reds[half][3]));

    __half2* ph2 = (__half2*)(Ph + (size_t)row * SEQ);
#pragma unroll
    for (int k = 0; k < 4; k++) {
        int base = (tr + k * 128) * 2;
        ph2[base + 0] = __halves2half2(__float2half(v[k].x * inv),
                                       __float2half(v[k].y * inv));
        ph2[base + 1] = __halves2half2(__float2half(v[k].z * inv),
                                       __float2half(v[k].w * inv));
    }
}

// ---------------------------------------------------------------------------
extern "C" void kernel_launch(void* const* d_in, const int* in_sizes, int n_in,
                              void* d_out, int out_size)
{
    const float* X  = (const float*)d_in[0];
    const float* Wq = (const float*)d_in[1];
    const float* Wk = (const float*)d_in[2];
    const float* Wv = (const float*)d_in[3];
    float* out = (float*)d_out;

    f16 *xh, *xl, *wth, *wtl, *qh, *ql, *kh, *kl, *vth, *ph;
    float* s;
    cudaGetSymbolAddress((void**)&xh, g_xh);
    cudaGetSymbolAddress((void**)&xl, g_xl);
    cudaGetSymbolAddress((void**)&wth, g_wth);
    cudaGetSymbolAddress((void**)&wtl, g_wtl);
    cudaGetSymbolAddress((void**)&qh, g_qh);
    cudaGetSymbolAddress((void**)&ql, g_ql);
    cudaGetSymbolAddress((void**)&kh, g_kh);
    cudaGetSymbolAddress((void**)&kl, g_kl);
    cudaGetSymbolAddress((void**)&vth, g_vth);
    cudaGetSymbolAddress((void**)&ph, g_ph);
    cudaGetSymbolAddress((void**)&s, g_s);

    cudaFuncSetAttribute(proj_fused, cudaFuncAttributeMaxDynamicSharedMemorySize, SMEMSZ3);
    cudaFuncSetAttribute(gemm_mma<3, 3>, cudaFuncAttributeMaxDynamicSharedMemorySize, SMEMSZ3);
    cudaFuncSetAttribute(gemm_mma<1, 6>, cudaFuncAttributeMaxDynamicSharedMemorySize, SMEMSZ1);

    const int nx = MTOT * DIM;
    xsplit_kernel<<<nx / 256, 256>>>(X, xh, xl, nx);
    dim3 gw(DIM / 32, DIM / 32, 3);
    wtrans_kernel<<<gw, dim3(32, 8)>>>(Wq, Wk, Wv, wth, wtl);

    // Fused QKV projection: grid 18 x 128
    dim3 gp(3 * DIM / 128, MTOT / 128, 1);
    proj_fused<<<gp, 128, SMEMSZ3>>>(xh, xl, wth, wtl, qh, ql, kh, kl, vth);

    // Scores: per batch S = Q * K^T, [2048,2048], K=768 (3-pass, 3-stage)
    dim3 gs(SEQ / 128, SEQ / 128, BSZ);
    gemm_mma<3, 3><<<gs, 128, SMEMSZ3>>>(qh, ql, kh, kl, s, DIM,
                                         (long)SEQ * DIM, (long)SEQ * DIM,
                                         (long)SEQ * SEQ, SEQ);

    softmax_kernel<<<BSZ * SEQ / 2, 256>>>(s, ph);

    // Out: per batch O = P * (V^T)^T, [2048,768], K=2048 (1-pass, 6-stage)
    dim3 go(DIM / 128, SEQ / 128, BSZ);
    gemm_mma<1, 6><<<go, 128, SMEMSZ1>>>(ph, nullptr, vth, nullptr, out, SEQ,
                                         (long)SEQ * SEQ, (long)DIM * SEQ,
                                         (long)SEQ * DIM, DIM);
}

// round 16
// speedup vs baseline: 1.0594x; 1.0296x over previous
#include <cuda_runtime.h>
#include <cuda_fp16.h>
#include <cstdint>

typedef __half f16;

constexpr int BSZ = 8, SEQ = 2048, DIM = 768;
constexpr int MTOT = BSZ * SEQ;            // 16384

// Swizzled smem tiles: 128 rows x 64B, chunk ^= (row>>1)&3  (16B chunks).
constexpr int TILE  = 8192;
constexpr int STB3  = 4 * TILE;            // 32768: Ah,Al,Bh,Bl
constexpr int STB1  = 2 * TILE;            // 16384: Ah,Bh (PV)
constexpr int SMEMSZ3 = 3 * STB3;          // 98304 (3-stage)
constexpr int SMEMSZ1 = 6 * STB1;          // 98304 (6-stage, PV)
// epi2 staging needs 128*129*4 = 66048 <= both

// ---------------- static device scratch (allocation-free rule) --------------
__device__ f16 g_xh[(size_t)MTOT * DIM];
__device__ f16 g_xl[(size_t)MTOT * DIM];
__device__ f16 g_wth[3][DIM * DIM];        // contiguous [2304 x 768] B^T
__device__ f16 g_wtl[3][DIM * DIM];
__device__ f16 g_qh[(size_t)MTOT * DIM];
__device__ f16 g_ql[(size_t)MTOT * DIM];
__device__ f16 g_kh[(size_t)MTOT * DIM];
__device__ f16 g_kl[(size_t)MTOT * DIM];
__device__ f16 g_vth[(size_t)MTOT * DIM];   // V^T per batch: [b][768][2048], hi only
__device__ float g_s[(size_t)BSZ * SEQ * SEQ];
__device__ f16 g_ph[(size_t)BSZ * SEQ * SEQ];

// ---------------- PTX helpers ----------------------------------------------
__device__ __forceinline__ uint32_t smem_u32(const void* p) {
    uint32_t a;
    asm("{ .reg .u64 t; cvta.to.shared.u64 t, %1; cvt.u32.u64 %0, t; }"
        : "=r"(a) : "l"(p));
    return a;
}

__device__ __forceinline__ void ldmx4(uint32_t* r, uint32_t a) {
    asm volatile("ldmatrix.sync.aligned.m8n8.x4.shared.b16 {%0,%1,%2,%3}, [%4];"
                 : "=r"(r[0]), "=r"(r[1]), "=r"(r[2]), "=r"(r[3]) : "r"(a));
}

__device__ __forceinline__ void mma_f16(float* c, const uint32_t* a, const uint32_t* b) {
    asm volatile(
        "mma.sync.aligned.m16n8k16.row.col.f32.f16.f16.f32 "
        "{%0,%1,%2,%3}, {%4,%5,%6,%7}, {%8,%9}, {%0,%1,%2,%3};"
        : "+f"(c[0]), "+f"(c[1]), "+f"(c[2]), "+f"(c[3])
        : "r"(a[0]), "r"(a[1]), "r"(a[2]), "r"(a[3]), "r"(b[0]), "r"(b[1]));
}

__device__ __forceinline__ void cpasync16(uint32_t s, const void* g) {
    asm volatile("cp.async.cg.shared.global [%0], [%1], 16;" :: "r"(s), "l"(g));
}

// swizzled in-tile offset for (row, 16B-chunk)
__device__ __forceinline__ uint32_t swz(int row, int ch) {
    return (uint32_t)(row * 64 + ((ch ^ ((row >> 1) & 3)) << 4));
}

// ---------------------------------------------------------------------------
// Fused QKV projection.  Grid (18, 128); n0 selects output + pass count:
//   n0 <  768 : Q hi/lo (3-pass)   n0 < 1536 : K hi/lo (3-pass)
//   else      : V^T hi  (2-pass)
// 3-stage cp.async pipeline; next-stage issue interleaved after ks=0 compute.
// 128 threads, 2 CTAs/SM.
// ---------------------------------------------------------------------------
__global__ void __launch_bounds__(128, 2)
proj_fused(const f16* __restrict__ Ah, const f16* __restrict__ Al,
           const f16* __restrict__ Bh, const f16* __restrict__ Bl,
           f16* __restrict__ Qh, f16* __restrict__ Ql,
           f16* __restrict__ Kh, f16* __restrict__ Kl,
           f16* __restrict__ Vt)
{
    extern __shared__ char smem[];
    const int tid = threadIdx.x, lane = tid & 31, wid = tid >> 5;
    const int m0 = blockIdx.y * 128, n0 = blockIdx.x * 128;
    const int warp_m = wid & 1, warp_n = wid >> 1;
    const bool three = (n0 < 1536);

    const char* pAh = (const char*)Ah;
    const char* pAl = (const char*)Al;
    const char* pBh = (const char*)Bh;
    const char* pBl = (const char*)Bl;

    const uint32_t sb = smem_u32(smem);
    const uint32_t rowbytes = DIM * 2;

    float acc[4][8][4];
#pragma unroll
    for (int t = 0; t < 4; t++)
#pragma unroll
        for (int j = 0; j < 8; j++)
#pragma unroll
            for (int c = 0; c < 4; c++) acc[t][j][c] = 0.0f;

#define PISSUE(kc, buf)                                                          \
    {                                                                            \
        uint32_t s0 = sb + (buf) * STB3;                                         \
        uint32_t kcb = (uint32_t)(kc) * 64;                                      \
        _Pragma("unroll")                                                        \
        for (int i = 0; i < 4; i++) {                                            \
            int c = tid + i * 128;                                               \
            int r = c >> 2, ch = c & 3;                                          \
            size_t goA = (size_t)(m0 + r) * rowbytes + kcb + ch * 16;            \
            size_t goB = (size_t)(n0 + r) * rowbytes + kcb + ch * 16;            \
            uint32_t so = swz(r, ch);                                            \
            cpasync16(s0 + 0 * TILE + so, pAh + goA);                            \
            cpasync16(s0 + 1 * TILE + so, pAl + goA);                            \
            cpasync16(s0 + 2 * TILE + so, pBh + goB);                            \
            if (three) cpasync16(s0 + 3 * TILE + so, pBl + goB);                 \
        }                                                                        \
        asm volatile("cp.async.commit_group;" ::: "memory");                     \
    }

    PISSUE(0, 0);
    PISSUE(1, 1);

    const int nch = DIM >> 5;   // 24
    int cb = 0, ib = 2;
    for (int kc = 0; kc < nch; kc++) {
        asm volatile("cp.async.wait_group 1;" ::: "memory");
        __syncthreads();

        const int knext = kc + 2;
        const uint32_t sA = sb + cb * STB3;
        cb = (cb + 1 == 3) ? 0 : cb + 1;

#pragma unroll
        for (int ks = 0; ks < 2; ks++) {
            uint32_t afh[4][4], afl[4][4];

            const int ra0 = warp_m * 64 + (lane & 15);
            const int ca = ks * 2 + (lane >> 4);
#pragma unroll
            for (int t = 0; t < 4; t++) {
                uint32_t ad = sA + swz(ra0 + t * 16, ca);
                ldmx4(afh[t], ad);
                ldmx4(afl[t], ad + TILE);
            }

            const int rb0 = warp_n * 64 + (lane >> 4) * 8 + (lane & 7);
            const int cbk = ks * 2 + ((lane >> 3) & 1);
#pragma unroll
            for (int jp = 0; jp < 4; jp++) {
                uint32_t bd = sA + 2 * TILE + swz(rb0 + jp * 16, cbk);
                uint32_t rh[4];
                ldmx4(rh, bd);
                const int j0 = jp * 2, j1 = jp * 2 + 1;
#pragma unroll
                for (int t = 0; t < 4; t++) {
                    mma_f16(acc[t][j0], afh[t], rh + 0);
                    mma_f16(acc[t][j1], afh[t], rh + 2);
                }
                if (three) {
                    uint32_t rl[4];
                    ldmx4(rl, bd + TILE);
#pragma unroll
                    for (int t = 0; t < 4; t++) {
                        mma_f16(acc[t][j0], afh[t], rl + 0);
                        mma_f16(acc[t][j1], afh[t], rl + 2);
                    }
                }
#pragma unroll
                for (int t = 0; t < 4; t++) {
                    mma_f16(acc[t][j0], afl[t], rh + 0);
                    mma_f16(acc[t][j1], afl[t], rh + 2);
                }
            }

            // interleave next-stage issue behind ks=0 compute
            if (ks == 0 && knext < nch) PISSUE(knext, ib);
        }
        ib = (ib + 1 == 3) ? 0 : ib + 1;
        __syncthreads();
    }
#undef PISSUE

    // ---------------- epilogue dispatch ----------------
    const int rbase = warp_m * 64 + (lane >> 2);
    const int cbase = warp_n * 64 + (lane & 3) * 2;

    if (three) {
        f16* Oh = (n0 < 768) ? Qh : Kh;
        f16* Ol = (n0 < 768) ? Ql : Kl;
        const int nc0 = (n0 < 768) ? n0 : n0 - 768;
#pragma unroll
        for (int t = 0; t < 4; t++)
#pragma unroll
            for (int j = 0; j < 8; j++)
#pragma unroll
                for (int h = 0; h < 2; h++) {
                    int rr = m0 + rbase + t * 16 + h * 8;
                    int cc = nc0 + cbase + j * 8;
                    float x0 = acc[t][j][h * 2 + 0], x1 = acc[t][j][h * 2 + 1];
                    f16 h0 = __float2half(x0), h1 = __float2half(x1);
                    f16 l0 = __float2half(x0 - __half2float(h0));
                    f16 l1 = __float2half(x1 - __half2float(h1));
                    *(__half2*)(Oh + (size_t)rr * DIM + cc) = __halves2half2(h0, h1);
                    *(__half2*)(Ol + (size_t)rr * DIM + cc) = __halves2half2(l0, l1);
                }
    } else {
        float* st = (float*)smem;
#pragma unroll
        for (int t = 0; t < 4; t++)
#pragma unroll
            for (int j = 0; j < 8; j++)
#pragma unroll
                for (int h = 0; h < 2; h++) {
                    int rr = rbase + t * 16 + h * 8;
                    int cc = cbase + j * 8;
                    st[(size_t)rr * 129 + cc + 0] = acc[t][j][h * 2 + 0];
                    st[(size_t)rr * 129 + cc + 1] = acc[t][j][h * 2 + 1];
                }
        __syncthreads();
        const int nv0 = n0 - 1536;
        for (int idx = tid; idx < 128 * 128; idx += 128) {
            int nl = idx >> 7, ml = idx & 127;
            int mg = m0 + ml;
            int b = mg >> 11, mloc = mg & 2047;
            float x = st[(size_t)ml * 129 + nl];
            size_t o = (size_t)b * DIM * SEQ + (size_t)(nv0 + nl) * SEQ + mloc;
            Vt[o] = __float2half(x);
        }
    }
}

// ---------------------------------------------------------------------------
// Batched GEMM: NPASS=3 (scores, 3-stage) / NPASS=1 (PV, 6-stage), fp32 out.
// Next-stage issue interleaved after ks=0 compute.
// 128 threads, tile 128x128, warp tile 64x64, 2 CTAs/SM, BK=32.
// ---------------------------------------------------------------------------
template <int NPASS, int NSTAGE>
__global__ void __launch_bounds__(128, 2)
gemm_mma(const f16* __restrict__ Ah, const f16* __restrict__ Al,
         const f16* __restrict__ Bh, const f16* __restrict__ Bl,
         float* __restrict__ O,
         int K, long batchA, long batchB, long batchC, int ldC)
{
    constexpr int STB  = (NPASS == 1) ? STB1 : STB3;
    constexpr int BOFF = (NPASS == 1) ? TILE : 2 * TILE;   // B_HI offset

    extern __shared__ char smem[];
    const int tid = threadIdx.x, lane = tid & 31, wid = tid >> 5;
    const int z = blockIdx.z;
    const int m0 = blockIdx.y * 128, n0 = blockIdx.x * 128;
    const int warp_m = wid & 1, warp_n = wid >> 1;

    const char* pAh = (const char*)(Ah + (size_t)z * batchA);
    const char* pAl = (NPASS == 3) ? (const char*)(Al + (size_t)z * batchA) : nullptr;
    const char* pBh = (const char*)(Bh + (size_t)z * batchB);
    const char* pBl = (NPASS == 3) ? (const char*)(Bl + (size_t)z * batchB) : nullptr;

    const uint32_t sb = smem_u32(smem);
    const uint32_t rowbytes = (uint32_t)K * 2;

    float acc[4][8][4];
#pragma unroll
    for (int t = 0; t < 4; t++)
#pragma unroll
        for (int j = 0; j < 8; j++)
#pragma unroll
            for (int c = 0; c < 4; c++) acc[t][j][c] = 0.0f;

    const int nch = K >> 5;

#define ISSUE(kc, buf)                                                           \
    {                                                                            \
        uint32_t s0 = sb + (buf) * STB;                                          \
        uint32_t kcb = (uint32_t)(kc) * 64;                                      \
        _Pragma("unroll")                                                        \
        for (int i = 0; i < 4; i++) {                                            \
            int c = tid + i * 128;                                               \
            int r = c >> 2, ch = c & 3;                                          \
            size_t goA = (size_t)(m0 + r) * rowbytes + kcb + ch * 16;            \
            size_t goB = (size_t)(n0 + r) * rowbytes + kcb + ch * 16;            \
            uint32_t so = swz(r, ch);                                            \
            cpasync16(s0 + so, pAh + goA);                                       \
            if (NPASS == 3) cpasync16(s0 + TILE + so, pAl + goA);                \
            cpasync16(s0 + BOFF + so, pBh + goB);                                \
            if (NPASS == 3) cpasync16(s0 + 3 * TILE + so, pBl + goB);            \
        }                                                                        \
        asm volatile("cp.async.commit_group;" ::: "memory");                     \
    }

#pragma unroll
    for (int p = 0; p < NSTAGE - 1; p++) ISSUE(p, p);

    int cb = 0, ib = NSTAGE - 1;
    for (int kc = 0; kc < nch; kc++) {
        asm volatile("cp.async.wait_group %0;" :: "n"(NSTAGE - 2) : "memory");
        __syncthreads();

        const int knext = kc + NSTAGE - 1;
        const uint32_t sA = sb + cb * STB;
        cb = (cb + 1 == NSTAGE) ? 0 : cb + 1;

#pragma unroll
        for (int ks = 0; ks < 2; ks++) {
            uint32_t afh[4][4], afl[4][4];

            const int ra0 = warp_m * 64 + (lane & 15);
            const int ca = ks * 2 + (lane >> 4);
#pragma unroll
            for (int t = 0; t < 4; t++) {
                uint32_t ad = sA + swz(ra0 + t * 16, ca);
                ldmx4(afh[t], ad);
                if (NPASS == 3) ldmx4(afl[t], ad + TILE);
            }

            const int rb0 = warp_n * 64 + (lane >> 4) * 8 + (lane & 7);
            const int cbk = ks * 2 + ((lane >> 3) & 1);
#pragma unroll
            for (int jp = 0; jp < 4; jp++) {
                uint32_t bd = sA + BOFF + swz(rb0 + jp * 16, cbk);
                uint32_t rh[4];
                ldmx4(rh, bd);
                const int j0 = jp * 2, j1 = jp * 2 + 1;
#pragma unroll
                for (int t = 0; t < 4; t++) {
                    mma_f16(acc[t][j0], afh[t], rh + 0);
                    mma_f16(acc[t][j1], afh[t], rh + 2);
                }
                if (NPASS == 3) {
                    uint32_t rl[4];
                    ldmx4(rl, bd + TILE);
#pragma unroll
                    for (int t = 0; t < 4; t++) {
                        mma_f16(acc[t][j0], afh[t], rl + 0);
                        mma_f16(acc[t][j1], afh[t], rl + 2);
                    }
#pragma unroll
                    for (int t = 0; t < 4; t++) {
                        mma_f16(acc[t][j0], afl[t], rh + 0);
                        mma_f16(acc[t][j1], afl[t], rh + 2);
                    }
                }
            }

            // interleave next-stage issue behind ks=0 compute
            if (ks == 0 && knext < nch) ISSUE(knext, ib);
        }
        ib = (ib + 1 == NSTAGE) ? 0 : ib + 1;
        __syncthreads();
    }
#undef ISSUE

    // fp32 epilogue
    const int rbase = warp_m * 64 + (lane >> 2);
    const int cbase = warp_n * 64 + (lane & 3) * 2;
    float* C = O + (size_t)z * batchC;
#pragma unroll
    for (int t = 0; t < 4; t++)
#pragma unroll
        for (int j = 0; j < 8; j++) {
            int rr = m0 + rbase + t * 16;
            int cc = n0 + cbase + j * 8;
            *(float2*)(C + (size_t)rr * ldC + cc) =
                make_float2(acc[t][j][0], acc[t][j][1]);
            *(float2*)(C + (size_t)(rr + 8) * ldC + cc) =
                make_float2(acc[t][j][2], acc[t][j][3]);
        }
}

// ---------------- prep: X hi/lo split (coalesced) ---------------------------
__global__ void xsplit_kernel(const float* __restrict__ X,
                              f16* __restrict__ H, f16* __restrict__ L, int n)
{
    int i = blockIdx.x * 256 + threadIdx.x;
    if (i < n) {
        float x = X[i];
        f16 h = __float2half(x);
        H[i] = h;
        L[i] = __float2half(x - __half2float(h));
    }
}

// ---------------- prep: tiled weight transpose + split (coalesced) ----------
__global__ void wtrans_kernel(const float* __restrict__ Wq,
                              const float* __restrict__ Wk,
                              const float* __restrict__ Wv,
                              f16* __restrict__ TH, f16* __restrict__ TL)
{
    __shared__ float t[32][33];
    const int w = blockIdx.z;
    const float* W = (w == 0) ? Wq : (w == 1) ? Wk : Wv;
    f16* th = TH + (size_t)w * DIM * DIM;
    f16* tl = TL + (size_t)w * DIM * DIM;

    const int f0 = blockIdx.x * 32;
    const int d0 = blockIdx.y * 32;
    const int tx = threadIdx.x, ty = threadIdx.y;

#pragma unroll
    for (int i = 0; i < 4; i++) {
        int d = d0 + ty + i * 8;
        t[ty + i * 8][tx] = W[(size_t)d * DIM + f0 + tx];
    }
    __syncthreads();

#pragma unroll
    for (int i = 0; i < 4; i++) {
        int f = f0 + ty + i * 8;
        float x = t[tx][ty + i * 8];
        f16 h = __float2half(x);
        size_t o = (size_t)f * DIM + d0 + tx;
        th[o] = h;
        tl[o] = __float2half(x - __half2float(h));
    }
}

// ---------------- softmax: 2 rows/CTA, shuffle reduce, __expf ---------------
__global__ void __launch_bounds__(256)
softmax_kernel(const float* __restrict__ S, f16* __restrict__ Ph)
{
    const int tid = threadIdx.x;
    const int half = tid >> 7;
    const int tr = tid & 127;
    const int lane = tid & 31;
    const int wir = (tid >> 5) & 3;
    const int row = blockIdx.x * 2 + half;

    const float4* p4 = (const float4*)(S + (size_t)row * SEQ);
    float4 v[4];
    float m = -1e30f;
#pragma unroll
    for (int k = 0; k < 4; k++) {
        v[k] = p4[tr + k * 128];
        m = fmaxf(m, fmaxf(fmaxf(v[k].x, v[k].y), fmaxf(v[k].z, v[k].w)));
    }
#pragma unroll
    for (int o = 16; o > 0; o >>= 1)
        m = fmaxf(m, __shfl_xor_sync(0xFFFFFFFF, m, o));

    __shared__ float redm[2][4];
    if (lane == 0) redm[half][wir] = m;
    __syncthreads();
    m = fmaxf(fmaxf(redm[half][0], redm[half][1]),
              fmaxf(redm[half][2], redm[half][3]));

    float sum = 0.0f;
#pragma unroll
    for (int k = 0; k < 4; k++) {
        v[k].x = __expf(v[k].x - m); v[k].y = __expf(v[k].y - m);
        v[k].z = __expf(v[k].z - m); v[k].w = __expf(v[k].w - m);
        sum += (v[k].x + v[k].y) + (v[k].z + v[k].w);
    }
#pragma unroll
    for (int o = 16; o > 0; o >>= 1)
        sum += __shfl_xor_sync(0xFFFFFFFF, sum, o);

    __shared__ float reds[2][4];
    if (lane == 0) reds[half][wir] = sum;
    __syncthreads();
    const float inv = 1.0f / ((reds[half][0] + reds[half][1]) +
                              (reds[half][2] + reds[half][3]));

    __half2* ph2 = (__half2*)(Ph + (size_t)row * SEQ);
#pragma unroll
    for (int k = 0; k < 4; k++) {
        int base = (tr + k * 128) * 2;
        ph2[base + 0] = __halves2half2(__float2half(v[k].x * inv),
                                       __float2half(v[k].y * inv));
        ph2[base + 1] = __halves2half2(__float2half(v[k].z * inv),
                                       __float2half(v[k].w * inv));
    }
}

// ---------------------------------------------------------------------------
extern "C" void kernel_launch(void* const* d_in, const int* in_sizes, int n_in,
                              void* d_out, int out_size)
{
    const float* X  = (const float*)d_in[0];
    const float* Wq = (const float*)d_in[1];
    const float* Wk = (const float*)d_in[2];
    const float* Wv = (const float*)d_in[3];
    float* out = (float*)d_out;

    f16 *xh, *xl, *wth, *wtl, *qh, *ql, *kh, *kl, *vth, *ph;
    float* s;
    cudaGetSymbolAddress((void**)&xh, g_xh);
    cudaGetSymbolAddress((void**)&xl, g_xl);
    cudaGetSymbolAddress((void**)&wth, g_wth);
    cudaGetSymbolAddress((void**)&wtl, g_wtl);
    cudaGetSymbolAddress((void**)&qh, g_qh);
    cudaGetSymbolAddress((void**)&ql, g_ql);
    cudaGetSymbolAddress((void**)&kh, g_kh);
    cudaGetSymbolAddress((void**)&kl, g_kl);
    cudaGetSymbolAddress((void**)&vth, g_vth);
    cudaGetSymbolAddress((void**)&ph, g_ph);
    cudaGetSymbolAddress((void**)&s, g_s);

    cudaFuncSetAttribute(proj_fused, cudaFuncAttributeMaxDynamicSharedMemorySize, SMEMSZ3);
    cudaFuncSetAttribute(gemm_mma<3, 3>, cudaFuncAttributeMaxDynamicSharedMemorySize, SMEMSZ3);
    cudaFuncSetAttribute(gemm_mma<1, 6>, cudaFuncAttributeMaxDynamicSharedMemorySize, SMEMSZ1);

    const int nx = MTOT * DIM;
    xsplit_kernel<<<nx / 256, 256>>>(X, xh, xl, nx);
    dim3 gw(DIM / 32, DIM / 32, 3);
    wtrans_kernel<<<gw, dim3(32, 8)>>>(Wq, Wk, Wv, wth, wtl);

    // Fused QKV projection: grid 18 x 128
    dim3 gp(3 * DIM / 128, MTOT / 128, 1);
    proj_fused<<<gp, 128, SMEMSZ3>>>(xh, xl, wth, wtl, qh, ql, kh, kl, vth);

    // Scores: per batch S = Q * K^T, [2048,2048], K=768 (3-pass, 3-stage)
    dim3 gs(SEQ / 128, SEQ / 128, BSZ);
    gemm_mma<3, 3><<<gs, 128, SMEMSZ3>>>(qh, ql, kh, kl, s, DIM,
                                         (long)SEQ * DIM, (long)SEQ * DIM,
                                         (long)SEQ * SEQ, SEQ);

    softmax_kernel<<<BSZ * SEQ / 2, 256>>>(s, ph);

    // Out: per batch O = P * (V^T)^T, [2048,768], K=2048 (1-pass, 6-stage)
    dim3 go(DIM / 128, SEQ / 128, BSZ);
    gemm_mma<1, 6><<<go, 128, SMEMSZ1>>>(ph, nullptr, vth, nullptr, out, SEQ,
                                         (long)SEQ * SEQ, (long)DIM * SEQ,
                                         (long)SEQ * DIM, DIM);
}

// round 17
// speedup vs baseline: 1.0596x; 1.0002x over previous
#include <cuda_runtime.h>
#include <cuda_fp16.h>
#include <cstdint>

typedef __half f16;

constexpr int BSZ = 8, SEQ = 2048, DIM = 768;
constexpr int MTOT = BSZ * SEQ;            // 16384

// Swizzled smem tiles: 128 rows x 64B, chunk ^= (row>>1)&3  (16B chunks).
constexpr int TILE  = 8192;
constexpr int STB3  = 4 * TILE;            // 32768: Ah,Al,Bh,Bl
constexpr int STB1  = 2 * TILE;            // 16384: Ah,Bh (PV)
constexpr int SMEMSZ3 = 3 * STB3;          // 98304 (3-stage)
constexpr int SMEMSZ1 = 6 * STB1;          // 98304 (6-stage, PV)
// epi2 staging needs 128*129*4 = 66048 <= both

// ---------------- static device scratch (allocation-free rule) --------------
__device__ f16 g_xh[(size_t)MTOT * DIM];
__device__ f16 g_xl[(size_t)MTOT * DIM];
__device__ f16 g_wth[3][DIM * DIM];        // contiguous [2304 x 768] B^T
__device__ f16 g_wtl[3][DIM * DIM];
__device__ f16 g_qh[(size_t)MTOT * DIM];
__device__ f16 g_ql[(size_t)MTOT * DIM];
__device__ f16 g_kh[(size_t)MTOT * DIM];
__device__ f16 g_kl[(size_t)MTOT * DIM];
__device__ f16 g_vth[(size_t)MTOT * DIM];   // V^T per batch: [b][768][2048], hi only
__device__ float g_s[(size_t)BSZ * SEQ * SEQ];
__device__ f16 g_ph[(size_t)BSZ * SEQ * SEQ];

// ---------------- PTX helpers ----------------------------------------------
__device__ __forceinline__ uint32_t smem_u32(const void* p) {
    uint32_t a;
    asm("{ .reg .u64 t; cvta.to.shared.u64 t, %1; cvt.u32.u64 %0, t; }"
        : "=r"(a) : "l"(p));
    return a;
}

__device__ __forceinline__ void ldmx4(uint32_t* r, uint32_t a) {
    asm volatile("ldmatrix.sync.aligned.m8n8.x4.shared.b16 {%0,%1,%2,%3}, [%4];"
                 : "=r"(r[0]), "=r"(r[1]), "=r"(r[2]), "=r"(r[3]) : "r"(a));
}

__device__ __forceinline__ void mma_f16(float* c, const uint32_t* a, const uint32_t* b) {
    asm volatile(
        "mma.sync.aligned.m16n8k16.row.col.f32.f16.f16.f32 "
        "{%0,%1,%2,%3}, {%4,%5,%6,%7}, {%8,%9}, {%0,%1,%2,%3};"
        : "+f"(c[0]), "+f"(c[1]), "+f"(c[2]), "+f"(c[3])
        : "r"(a[0]), "r"(a[1]), "r"(a[2]), "r"(a[3]), "r"(b[0]), "r"(b[1]));
}

__device__ __forceinline__ void cpasync16(uint32_t s, const void* g) {
    asm volatile("cp.async.cg.shared.global [%0], [%1], 16;" :: "r"(s), "l"(g));
}

// swizzled in-tile offset for (row, 16B-chunk)
__device__ __forceinline__ uint32_t swz(int row, int ch) {
    return (uint32_t)(row * 64 + ((ch ^ ((row >> 1) & 3)) << 4));
}

// ---------------------------------------------------------------------------
// Fused QKV projection.  Grid (18, 128); n0 selects output + pass count:
//   n0 <  768 : Q hi/lo (3-pass)   n0 < 1536 : K hi/lo (3-pass)
//   else      : V^T hi  (2-pass)
// 3-stage cp.async pipeline; next-stage issue interleaved after ks=0 compute.
// Single barrier per mainloop iteration.  128 threads, 2 CTAs/SM.
// ---------------------------------------------------------------------------
__global__ void __launch_bounds__(128, 2)
proj_fused(const f16* __restrict__ Ah, const f16* __restrict__ Al,
           const f16* __restrict__ Bh, const f16* __restrict__ Bl,
           f16* __restrict__ Qh, f16* __restrict__ Ql,
           f16* __restrict__ Kh, f16* __restrict__ Kl,
           f16* __restrict__ Vt)
{
    extern __shared__ char smem[];
    const int tid = threadIdx.x, lane = tid & 31, wid = tid >> 5;
    const int m0 = blockIdx.y * 128, n0 = blockIdx.x * 128;
    const int warp_m = wid & 1, warp_n = wid >> 1;
    const bool three = (n0 < 1536);

    const char* pAh = (const char*)Ah;
    const char* pAl = (const char*)Al;
    const char* pBh = (const char*)Bh;
    const char* pBl = (const char*)Bl;

    const uint32_t sb = smem_u32(smem);
    const uint32_t rowbytes = DIM * 2;

    float acc[4][8][4];
#pragma unroll
    for (int t = 0; t < 4; t++)
#pragma unroll
        for (int j = 0; j < 8; j++)
#pragma unroll
            for (int c = 0; c < 4; c++) acc[t][j][c] = 0.0f;

#define PISSUE(kc, buf)                                                          \
    {                                                                            \
        uint32_t s0 = sb + (buf) * STB3;                                         \
        uint32_t kcb = (uint32_t)(kc) * 64;                                      \
        _Pragma("unroll")                                                        \
        for (int i = 0; i < 4; i++) {                                            \
            int c = tid + i * 128;                                               \
            int r = c >> 2, ch = c & 3;                                          \
            size_t goA = (size_t)(m0 + r) * rowbytes + kcb + ch * 16;            \
            size_t goB = (size_t)(n0 + r) * rowbytes + kcb + ch * 16;            \
            uint32_t so = swz(r, ch);                                            \
            cpasync16(s0 + 0 * TILE + so, pAh + goA);                            \
            cpasync16(s0 + 1 * TILE + so, pAl + goA);                            \
            cpasync16(s0 + 2 * TILE + so, pBh + goB);                            \
            if (three) cpasync16(s0 + 3 * TILE + so, pBl + goB);                 \
        }                                                                        \
        asm volatile("cp.async.commit_group;" ::: "memory");                     \
    }

    PISSUE(0, 0);
    PISSUE(1, 1);

    const int nch = DIM >> 5;   // 24
    int cb = 0, ib = 2;
    for (int kc = 0; kc < nch; kc++) {
        asm volatile("cp.async.wait_group 1;" ::: "memory");
        __syncthreads();   // single barrier: orders cp.async visibility AND
                           // buffer-reuse (a warp passing it implies all warps
                           // completed the previous iteration's reads)

        const int knext = kc + 2;
        const uint32_t sA = sb + cb * STB3;
        cb = (cb + 1 == 3) ? 0 : cb + 1;

#pragma unroll
        for (int ks = 0; ks < 2; ks++) {
            uint32_t afh[4][4], afl[4][4];

            const int ra0 = warp_m * 64 + (lane & 15);
            const int ca = ks * 2 + (lane >> 4);
#pragma unroll
            for (int t = 0; t < 4; t++) {
                uint32_t ad = sA + swz(ra0 + t * 16, ca);
                ldmx4(afh[t], ad);
                ldmx4(afl[t], ad + TILE);
            }

            const int rb0 = warp_n * 64 + (lane >> 4) * 8 + (lane & 7);
            const int cbk = ks * 2 + ((lane >> 3) & 1);
#pragma unroll
            for (int jp = 0; jp < 4; jp++) {
                uint32_t bd = sA + 2 * TILE + swz(rb0 + jp * 16, cbk);
                uint32_t rh[4];
                ldmx4(rh, bd);
                const int j0 = jp * 2, j1 = jp * 2 + 1;
#pragma unroll
                for (int t = 0; t < 4; t++) {
                    mma_f16(acc[t][j0], afh[t], rh + 0);
                    mma_f16(acc[t][j1], afh[t], rh + 2);
                }
                if (three) {
                    uint32_t rl[4];
                    ldmx4(rl, bd + TILE);
#pragma unroll
                    for (int t = 0; t < 4; t++) {
                        mma_f16(acc[t][j0], afh[t], rl + 0);
                        mma_f16(acc[t][j1], afh[t], rl + 2);
                    }
                }
#pragma unroll
                for (int t = 0; t < 4; t++) {
                    mma_f16(acc[t][j0], afl[t], rh + 0);
                    mma_f16(acc[t][j1], afl[t], rh + 2);
                }
            }

            // interleave next-stage issue behind ks=0 compute
            if (ks == 0 && knext < nch) PISSUE(knext, ib);
        }
        ib = (ib + 1 == 3) ? 0 : ib + 1;
    }
#undef PISSUE

    __syncthreads();   // all warps done with mainloop smem before epi reuse

    // ---------------- epilogue dispatch ----------------
    const int rbase = warp_m * 64 + (lane >> 2);
    const int cbase = warp_n * 64 + (lane & 3) * 2;

    if (three) {
        f16* Oh = (n0 < 768) ? Qh : Kh;
        f16* Ol = (n0 < 768) ? Ql : Kl;
        const int nc0 = (n0 < 768) ? n0 : n0 - 768;
#pragma unroll
        for (int t = 0; t < 4; t++)
#pragma unroll
            for (int j = 0; j < 8; j++)
#pragma unroll
                for (int h = 0; h < 2; h++) {
                    int rr = m0 + rbase + t * 16 + h * 8;
                    int cc = nc0 + cbase + j * 8;
                    float x0 = acc[t][j][h * 2 + 0], x1 = acc[t][j][h * 2 + 1];
                    f16 h0 = __float2half(x0), h1 = __float2half(x1);
                    f16 l0 = __float2half(x0 - __half2float(h0));
                    f16 l1 = __float2half(x1 - __half2float(h1));
                    *(__half2*)(Oh + (size_t)rr * DIM + cc) = __halves2half2(h0, h1);
                    *(__half2*)(Ol + (size_t)rr * DIM + cc) = __halves2half2(l0, l1);
                }
    } else {
        float* st = (float*)smem;
#pragma unroll
        for (int t = 0; t < 4; t++)
#pragma unroll
            for (int j = 0; j < 8; j++)
#pragma unroll
                for (int h = 0; h < 2; h++) {
                    int rr = rbase + t * 16 + h * 8;
                    int cc = cbase + j * 8;
                    st[(size_t)rr * 129 + cc + 0] = acc[t][j][h * 2 + 0];
                    st[(size_t)rr * 129 + cc + 1] = acc[t][j][h * 2 + 1];
                }
        __syncthreads();
        const int nv0 = n0 - 1536;
        for (int idx = tid; idx < 128 * 128; idx += 128) {
            int nl = idx >> 7, ml = idx & 127;
            int mg = m0 + ml;
            int b = mg >> 11, mloc = mg & 2047;
            float x = st[(size_t)ml * 129 + nl];
            size_t o = (size_t)b * DIM * SEQ + (size_t)(nv0 + nl) * SEQ + mloc;
            Vt[o] = __float2half(x);
        }
    }
}

// ---------------------------------------------------------------------------
// Batched GEMM: NPASS=3 (scores, 3-stage) / NPASS=1 (PV, 6-stage), fp32 out.
// Next-stage issue interleaved after ks=0; single barrier per iteration.
// 128 threads, tile 128x128, warp tile 64x64, 2 CTAs/SM, BK=32.
// ---------------------------------------------------------------------------
template <int NPASS, int NSTAGE>
__global__ void __launch_bounds__(128, 2)
gemm_mma(const f16* __restrict__ Ah, const f16* __restrict__ Al,
         const f16* __restrict__ Bh, const f16* __restrict__ Bl,
         float* __restrict__ O,
         int K, long batchA, long batchB, long batchC, int ldC)
{
    constexpr int STB  = (NPASS == 1) ? STB1 : STB3;
    constexpr int BOFF = (NPASS == 1) ? TILE : 2 * TILE;   // B_HI offset

    extern __shared__ char smem[];
    const int tid = threadIdx.x, lane = tid & 31, wid = tid >> 5;
    const int z = blockIdx.z;
    const int m0 = blockIdx.y * 128, n0 = blockIdx.x * 128;
    const int warp_m = wid & 1, warp_n = wid >> 1;

    const char* pAh = (const char*)(Ah + (size_t)z * batchA);
    const char* pAl = (NPASS == 3) ? (const char*)(Al + (size_t)z * batchA) : nullptr;
    const char* pBh = (const char*)(Bh + (size_t)z * batchB);
    const char* pBl = (NPASS == 3) ? (const char*)(Bl + (size_t)z * batchB) : nullptr;

    const uint32_t sb = smem_u32(smem);
    const uint32_t rowbytes = (uint32_t)K * 2;

    float acc[4][8][4];
#pragma unroll
    for (int t = 0; t < 4; t++)
#pragma unroll
        for (int j = 0; j < 8; j++)
#pragma unroll
            for (int c = 0; c < 4; c++) acc[t][j][c] = 0.0f;

    const int nch = K >> 5;

#define ISSUE(kc, buf)                                                           \
    {                                                                            \
        uint32_t s0 = sb + (buf) * STB;                                          \
        uint32_t kcb = (uint32_t)(kc) * 64;                                      \
        _Pragma("unroll")                                                        \
        for (int i = 0; i < 4; i++) {                                            \
            int c = tid + i * 128;                                               \
            int r = c >> 2, ch = c & 3;                                          \
            size_t goA = (size_t)(m0 + r) * rowbytes + kcb + ch * 16;            \
            size_t goB = (size_t)(n0 + r) * rowbytes + kcb + ch * 16;            \
            uint32_t so = swz(r, ch);                                            \
            cpasync16(s0 + so, pAh + goA);                                       \
            if (NPASS == 3) cpasync16(s0 + TILE + so, pAl + goA);                \
            cpasync16(s0 + BOFF + so, pBh + goB);                                \
            if (NPASS == 3) cpasync16(s0 + 3 * TILE + so, pBl + goB);            \
        }                                                                        \
        asm volatile("cp.async.commit_group;" ::: "memory");                     \
    }

#pragma unroll
    for (int p = 0; p < NSTAGE - 1; p++) ISSUE(p, p);

    int cb = 0, ib = NSTAGE - 1;
    for (int kc = 0; kc < nch; kc++) {
        asm volatile("cp.async.wait_group %0;" :: "n"(NSTAGE - 2) : "memory");
        __syncthreads();   // single barrier per iteration (see proj note)

        const int knext = kc + NSTAGE - 1;
        const uint32_t sA = sb + cb * STB;
        cb = (cb + 1 == NSTAGE) ? 0 : cb + 1;

#pragma unroll
        for (int ks = 0; ks < 2; ks++) {
            uint32_t afh[4][4], afl[4][4];

            const int ra0 = warp_m * 64 + (lane & 15);
            const int ca = ks * 2 + (lane >> 4);
#pragma unroll
            for (int t = 0; t < 4; t++) {
                uint32_t ad = sA + swz(ra0 + t * 16, ca);
                ldmx4(afh[t], ad);
                if (NPASS == 3) ldmx4(afl[t], ad + TILE);
            }

            const int rb0 = warp_n * 64 + (lane >> 4) * 8 + (lane & 7);
            const int cbk = ks * 2 + ((lane >> 3) & 1);
#pragma unroll
            for (int jp = 0; jp < 4; jp++) {
                uint32_t bd = sA + BOFF + swz(rb0 + jp * 16, cbk);
                uint32_t rh[4];
                ldmx4(rh, bd);
                const int j0 = jp * 2, j1 = jp * 2 + 1;
#pragma unroll
                for (int t = 0; t < 4; t++) {
                    mma_f16(acc[t][j0], afh[t], rh + 0);
                    mma_f16(acc[t][j1], afh[t], rh + 2);
                }
                if (NPASS == 3) {
                    uint32_t rl[4];
                    ldmx4(rl, bd + TILE);
#pragma unroll
                    for (int t = 0; t < 4; t++) {
                        mma_f16(acc[t][j0], afh[t], rl + 0);
                        mma_f16(acc[t][j1], afh[t], rl + 2);
                    }
#pragma unroll
                    for (int t = 0; t < 4; t++) {
                        mma_f16(acc[t][j0], afl[t], rh + 0);
                        mma_f16(acc[t][j1], afl[t], rh + 2);
                    }
                }
            }

            // interleave next-stage issue behind ks=0 compute
            if (ks == 0 && knext < nch) ISSUE(knext, ib);
        }
        ib = (ib + 1 == NSTAGE) ? 0 : ib + 1;
    }
#undef ISSUE

    // fp32 epilogue (registers only; no smem reuse -> no sync needed)
    const int rbase = warp_m * 64 + (lane >> 2);
    const int cbase = warp_n * 64 + (lane & 3) * 2;
    float* C = O + (size_t)z * batchC;
#pragma unroll
    for (int t = 0; t < 4; t++)
#pragma unroll
        for (int j = 0; j < 8; j++) {
            int rr = m0 + rbase + t * 16;
            int cc = n0 + cbase + j * 8;
            *(float2*)(C + (size_t)rr * ldC + cc) =
                make_float2(acc[t][j][0], acc[t][j][1]);
            *(float2*)(C + (size_t)(rr + 8) * ldC + cc) =
                make_float2(acc[t][j][2], acc[t][j][3]);
        }
}

// ---------------- prep: X hi/lo split (coalesced) ---------------------------
__global__ void xsplit_kernel(const float* __restrict__ X,
                              f16* __restrict__ H, f16* __restrict__ L, int n)
{
    int i = blockIdx.x * 256 + threadIdx.x;
    if (i < n) {
        float x = X[i];
        f16 h = __float2half(x);
        H[i] = h;
        L[i] = __float2half(x - __half2float(h));
    }
}

// ---------------- prep: tiled weight transpose + split (coalesced) ----------
__global__ void wtrans_kernel(const float* __restrict__ Wq,
                              const float* __restrict__ Wk,
                              const float* __restrict__ Wv,
                              f16* __restrict__ TH, f16* __restrict__ TL)
{
    __shared__ float t[32][33];
    const int w = blockIdx.z;
    const float* W = (w == 0) ? Wq : (w == 1) ? Wk : Wv;
    f16* th = TH + (size_t)w * DIM * DIM;
    f16* tl = TL + (size_t)w * DIM * DIM;

    const int f0 = blockIdx.x * 32;
    const int d0 = blockIdx.y * 32;
    const int tx = threadIdx.x, ty = threadIdx.y;

#pragma unroll
    for (int i = 0; i < 4; i++) {
        int d = d0 + ty + i * 8;
        t[ty + i * 8][tx] = W[(size_t)d * DIM + f0 + tx];
    }
    __syncthreads();

#pragma unroll
    for (int i = 0; i < 4; i++) {
        int f = f0 + ty + i * 8;
        float x = t[tx][ty + i * 8];
        f16 h = __float2half(x);
        size_t o = (size_t)f * DIM + d0 + tx;
        th[o] = h;
        tl[o] = __float2half(x - __half2float(h));
    }
}

// ---------------- softmax: 2 rows/CTA, shuffle reduce, __expf ---------------
__global__ void __launch_bounds__(256)
softmax_kernel(const float* __restrict__ S, f16* __restrict__ Ph)
{
    const int tid = threadIdx.x;
    const int half = tid >> 7;
    const int tr = tid & 127;
    const int lane = tid & 31;
    const int wir = (tid >> 5) & 3;
    const int row = blockIdx.x * 2 + half;

    const float4* p4 = (const float4*)(S + (size_t)row * SEQ);
    float4 v[4];
    float m = -1e30f;
#pragma unroll
    for (int k = 0; k < 4; k++) {
        v[k] = p4[tr + k * 128];
        m = fmaxf(m, fmaxf(fmaxf(v[k].x, v[k].y), fmaxf(v[k].z, v[k].w)));
    }
#pragma unroll
    for (int o = 16; o > 0; o >>= 1)
        m = fmaxf(m, __shfl_xor_sync(0xFFFFFFFF, m, o));

    __shared__ float redm[2][4];
    if (lane == 0) redm[half][wir] = m;
    __syncthreads();
    m = fmaxf(fmaxf(redm[half][0], redm[half][1]),
              fmaxf(redm[half][2], redm[half][3]));

    float sum = 0.0f;
#pragma unroll
    for (int k = 0; k < 4; k++) {
        v[k].x = __expf(v[k].x - m); v[k].y = __expf(v[k].y - m);
        v[k].z = __expf(v[k].z - m); v[k].w = __expf(v[k].w - m);
        sum += (v[k].x + v[k].y) + (v[k].z + v[k].w);
    }
#pragma unroll
    for (int o = 16; o > 0; o >>= 1)
        sum += __shfl_xor_sync(0xFFFFFFFF, sum, o);

    __shared__ float reds[2][4];
    if (lane == 0) reds[half][wir] = sum;
    __syncthreads();
    const float inv = 1.0f / ((reds[half][0] + reds[half][1]) +
                              (reds[half][2] + reds[half][3]));

    __half2* ph2 = (__half2*)(Ph + (size_t)row * SEQ);
#pragma unroll
    for (int k = 0; k < 4; k++) {
        int base = (tr + k * 128) * 2;
        ph2[base + 0] = __halves2half2(__float2half(v[k].x * inv),
                                       __float2half(v[k].y * inv));
        ph2[base + 1] = __halves2half2(__float2half(v[k].z * inv),
                                       __float2half(v[k].w * inv));
    }
}

// ---------------------------------------------------------------------------
extern "C" void kernel_launch(void* const* d_in, const int* in_sizes, int n_in,
                              void* d_out, int out_size)
{
    const float* X  = (const float*)d_in[0];
    const float* Wq = (const float*)d_in[1];
    const float* Wk = (const float*)d_in[2];
    const float* Wv = (const float*)d_in[3];
    float* out = (float*)d_out;

    f16 *xh, *xl, *wth, *wtl, *qh, *ql, *kh, *kl, *vth, *ph;
    float* s;
    cudaGetSymbolAddress((void**)&xh, g_xh);
    cudaGetSymbolAddress((void**)&xl, g_xl);
    cudaGetSymbolAddress((void**)&wth, g_wth);
    cudaGetSymbolAddress((void**)&wtl, g_wtl);
    cudaGetSymbolAddress((void**)&qh, g_qh);
    cudaGetSymbolAddress((void**)&ql, g_ql);
    cudaGetSymbolAddress((void**)&kh, g_kh);
    cudaGetSymbolAddress((void**)&kl, g_kl);
    cudaGetSymbolAddress((void**)&vth, g_vth);
    cudaGetSymbolAddress((void**)&ph, g_ph);
    cudaGetSymbolAddress((void**)&s, g_s);

    cudaFuncSetAttribute(proj_fused, cudaFuncAttributeMaxDynamicSharedMemorySize, SMEMSZ3);
    cudaFuncSetAttribute(gemm_mma<3, 3>, cudaFuncAttributeMaxDynamicSharedMemorySize, SMEMSZ3);
    cudaFuncSetAttribute(gemm_mma<1, 6>, cudaFuncAttributeMaxDynamicSharedMemorySize, SMEMSZ1);

    const int nx = MTOT * DIM;
    xsplit_kernel<<<nx / 256, 256>>>(X, xh, xl, nx);
    dim3 gw(DIM / 32, DIM / 32, 3);
    wtrans_kernel<<<gw, dim3(32, 8)>>>(Wq, Wk, Wv, wth, wtl);

    // Fused QKV projection: grid 18 x 128
    dim3 gp(3 * DIM / 128, MTOT / 128, 1);
    proj_fused<<<gp, 128, SMEMSZ3>>>(xh, xl, wth, wtl, qh, ql, kh, kl, vth);

    // Scores: per batch S = Q * K^T, [2048,2048], K=768 (3-pass, 3-stage)
    dim3 gs(SEQ / 128, SEQ / 128, BSZ);
    gemm_mma<3, 3><<<gs, 128, SMEMSZ3>>>(qh, ql, kh, kl, s, DIM,
                                         (long)SEQ * DIM, (long)SEQ * DIM,
                                         (long)SEQ * SEQ, SEQ);

    softmax_kernel<<<BSZ * SEQ / 2, 256>>>(s, ph);

    // Out: per batch O = P * (V^T)^T, [2048,768], K=2048 (1-pass, 6-stage)
    dim3 go(DIM / 128, SEQ / 128, BSZ);
    gemm_mma<1, 6><<<go, 128, SMEMSZ1>>>(ph, nullptr, vth, nullptr, out, SEQ,
                                         (long)SEQ * SEQ, (long)DIM * SEQ,
                                         (long)SEQ * DIM, DIM);
}